// round 1
// baseline (speedup 1.0000x reference)
#include <cuda_runtime.h>
#include <math.h>

#define BB   16
#define SSZ  1024
#define DDIM 512
#define BSN  (BB*SSZ)   // 16384 rows

// ---------------- scratch (device globals: allocation-free) ----------------
__device__ float g_conv [BB*SSZ*DDIM];
__device__ float g_n1   [BB*SSZ*DDIM];
__device__ float g_dense[BB*SSZ*DDIM];
__device__ float g_q    [BB*SSZ*DDIM];
__device__ float g_k    [BB*SSZ*DDIM];
__device__ float g_v    [BB*SSZ*DDIM];
__device__ float g_attn [BB*SSZ*DDIM];
__device__ float g_res  [BB*SSZ*DDIM];

// ---------------- kernel 1: conv + pe + gelu + LN1 -------------------------
// grid = 16384 (one per (b,s)), block = 128. Layout (B,S,D).
__global__ __launch_bounds__(128) void k_embed(
    const float* __restrict__ ts, const float* __restrict__ cw,
    const float* __restrict__ cb, const float* __restrict__ pe,
    const float* __restrict__ g1, const float* __restrict__ b1,
    float* __restrict__ convo, float* __restrict__ n1o)
{
    const int bs = blockIdx.x;
    const int b = bs >> 10, s = bs & 1023;
    const int t = threadIdx.x;
    const float* tp = ts + ((size_t)b << 12) + (s << 2);
    const float t0 = tp[0], t1 = tp[1], t2 = tp[2], t3 = tp[3];

    float act[4];
    float ls1 = 0.f, ls2 = 0.f;
#pragma unroll
    for (int r = 0; r < 4; r++) {
        const int d = t + (r << 7);
        const float4 w = *(const float4*)(cw + (d << 2));
        float c = fmaf(t0, w.x, fmaf(t1, w.y, fmaf(t2, w.z, t3 * w.w)));
        c += cb[d] + pe[((size_t)s << 9) + d];
        convo[((size_t)bs << 9) + d] = c;
        const float a = 0.5f * c * (1.0f + erff(c * 0.70710678118654752f));
        act[r] = a; ls1 += a; ls2 += a * a;
    }
    __shared__ float sa[4], sb[4];
#pragma unroll
    for (int o = 16; o; o >>= 1) {
        ls1 += __shfl_down_sync(0xffffffffu, ls1, o);
        ls2 += __shfl_down_sync(0xffffffffu, ls2, o);
    }
    if ((t & 31) == 0) { sa[t >> 5] = ls1; sb[t >> 5] = ls2; }
    __syncthreads();
    const float S1 = sa[0] + sa[1] + sa[2] + sa[3];
    const float S2 = sb[0] + sb[1] + sb[2] + sb[3];
    const float mean = S1 * (1.0f / 512.0f);
    const float var  = (S2 - 512.0f * mean * mean) * (1.0f / 511.0f);  // ddof=1
    const float rstd = rsqrtf(var + 1e-5f);
    const float gg = g1[s], be = b1[s];
#pragma unroll
    for (int r = 0; r < 4; r++) {
        const int d = t + (r << 7);
        n1o[((size_t)bs << 9) + d] = gg * (act[r] - mean) * rstd + be;
    }
}

// ---------------- generic SGEMM-NT with fused epilogues ---------------------
// C[m,e] = sum_d A[m,d] * Bw[e,d], M=16384, N=K=512.
// mode 0: += ts_emb[te[b], e]   (aux1=ts_emb, te)
// mode 1: *= 0.125f             (Q scale)
// mode 2: plain                 (K, V)
// mode 3: += bo[e] + conv[m,e]  (aux1=bo, aux2=conv residual)
__global__ __launch_bounds__(256) void sgemm_nt(
    const float* __restrict__ A, const float* __restrict__ Bw, float* __restrict__ C,
    int mode, const int* __restrict__ te,
    const float* __restrict__ aux1, const float* __restrict__ aux2)
{
    __shared__ __align__(16) float As[8][128];
    __shared__ __align__(16) float Bs[8][128];
    const int t = threadIdx.x;
    const int row0 = blockIdx.y << 7, col0 = blockIdx.x << 7;
    const int lr = t >> 1, lc = (t & 1) << 2;
    const float* Ag = A  + ((size_t)(row0 + lr) << 9) + lc;
    const float* Bg = Bw + ((size_t)(col0 + lr) << 9) + lc;
    const int tx = t & 15, ty = t >> 4;

    float acc[8][8];
#pragma unroll
    for (int i = 0; i < 8; i++)
#pragma unroll
        for (int j = 0; j < 8; j++) acc[i][j] = 0.f;

    float4 av = *(const float4*)Ag;
    float4 bv = *(const float4*)Bg;

    for (int k0 = 0; k0 < 512; k0 += 8) {
        __syncthreads();
        As[lc][lr] = av.x; As[lc + 1][lr] = av.y; As[lc + 2][lr] = av.z; As[lc + 3][lr] = av.w;
        Bs[lc][lr] = bv.x; Bs[lc + 1][lr] = bv.y; Bs[lc + 2][lr] = bv.z; Bs[lc + 3][lr] = bv.w;
        __syncthreads();
        if (k0 < 504) {
            av = *(const float4*)(Ag + k0 + 8);
            bv = *(const float4*)(Bg + k0 + 8);
        }
#pragma unroll
        for (int k = 0; k < 8; k++) {
            const float4 a0 = *(const float4*)(&As[k][ty << 3]);
            const float4 a1 = *(const float4*)(&As[k][(ty << 3) + 4]);
            const float4 b0 = *(const float4*)(&Bs[k][tx << 3]);
            const float4 b1 = *(const float4*)(&Bs[k][(tx << 3) + 4]);
            const float aa[8] = {a0.x, a0.y, a0.z, a0.w, a1.x, a1.y, a1.z, a1.w};
            const float bb[8] = {b0.x, b0.y, b0.z, b0.w, b1.x, b1.y, b1.z, b1.w};
#pragma unroll
            for (int i = 0; i < 8; i++)
#pragma unroll
                for (int j = 0; j < 8; j++) acc[i][j] = fmaf(aa[i], bb[j], acc[i][j]);
        }
    }

    const int bidx = row0 >> 10;       // whole 128-row tile lies in one batch b
    float addc[8];
#pragma unroll
    for (int j = 0; j < 8; j++) addc[j] = 0.f;
    if (mode == 0) {
        const int e = te[bidx];
#pragma unroll
        for (int j = 0; j < 8; j++) addc[j] = aux1[((size_t)e << 9) + col0 + (tx << 3) + j];
    } else if (mode == 3) {
#pragma unroll
        for (int j = 0; j < 8; j++) addc[j] = aux1[col0 + (tx << 3) + j];
    }

#pragma unroll
    for (int i = 0; i < 8; i++) {
        const int row = row0 + (ty << 3) + i;
        float o[8];
#pragma unroll
        for (int j = 0; j < 8; j++) {
            float v = acc[i][j];
            if (mode == 1) v *= 0.125f;
            v += addc[j];
            if (mode == 3) v += aux2[((size_t)row << 9) + col0 + (tx << 3) + j];
            o[j] = v;
        }
        float* cp = C + ((size_t)row << 9) + col0 + (tx << 3);
        *(float4*)cp       = make_float4(o[0], o[1], o[2], o[3]);
        *(float4*)(cp + 4) = make_float4(o[4], o[5], o[6], o[7]);
    }
}

// ---------------- kernel 3: "transposed" causal flash attention -------------
// out[j] = sum_{i<=j} softmax_i(k_j . q_i) v_i   (Q pre-scaled by 1/sqrt(DH))
// grid (S/64, H, B), 128 threads. j-tile 64 resident (K rows), i-tiles of 32.
#define SW 68
__global__ __launch_bounds__(128) void k_attn(
    const float* __restrict__ Qm, const float* __restrict__ Km,
    const float* __restrict__ Vm, float* __restrict__ Om)
{
    __shared__ __align__(16) float Ks[64 * SW];
    __shared__ __align__(16) float Qs[32 * SW];
    __shared__ __align__(16) float Vs[32 * SW];
    __shared__ __align__(16) float Ss[32 * SW];
    __shared__ float scl[64];
    __shared__ float lb[64];

    const int jt = blockIdx.x, h = blockIdx.y, b = blockIdx.z;
    const int j0 = jt << 6;
    const int t = threadIdx.x;
    const size_t base = ((size_t)b << 19) + (h << 6);   // (b*1024)*512 + h*64
    const int r0 = t >> 4, c4 = (t & 15) << 2;

#pragma unroll
    for (int rr = 0; rr < 8; rr++) {
        const int r = r0 + (rr << 3);
        *(float4*)(Ks + r * SW + c4) =
            *(const float4*)(Km + base + ((size_t)(j0 + r) << 9) + c4);
    }

    float mcol = -INFINITY, lcol = 0.f;
    float acc[4][8];
#pragma unroll
    for (int u = 0; u < 4; u++)
#pragma unroll
        for (int v = 0; v < 8; v++) acc[u][v] = 0.f;

    const int tjj = (t & 15) << 2, tcc = (t >> 4) << 3;  // PV tile (jj, c)
    const int sii = (t >> 4) << 2, sjj = (t & 15) << 2;  // score tile (ii, jj)
    const int ntiles = (jt << 1) + 2;

    for (int it = 0; it < ntiles; ++it) {
        const int i0 = it << 5;
        __syncthreads();
#pragma unroll
        for (int rr = 0; rr < 4; rr++) {
            const int r = r0 + (rr << 3);
            *(float4*)(Qs + r * SW + c4) =
                *(const float4*)(Qm + base + ((size_t)(i0 + r) << 9) + c4);
            *(float4*)(Vs + r * SW + c4) =
                *(const float4*)(Vm + base + ((size_t)(i0 + r) << 9) + c4);
        }
        __syncthreads();

        // scores: S[ii][jj] = q_{i0+ii} . k_{j0+jj} (already scaled)
        float sreg[4][4];
#pragma unroll
        for (int u = 0; u < 4; u++)
#pragma unroll
            for (int v = 0; v < 4; v++) sreg[u][v] = 0.f;
#pragma unroll
        for (int c = 0; c < 64; c += 4) {
            float4 qv[4], kv[4];
#pragma unroll
            for (int u = 0; u < 4; u++) qv[u] = *(const float4*)(Qs + (sii + u) * SW + c);
#pragma unroll
            for (int v = 0; v < 4; v++) kv[v] = *(const float4*)(Ks + (sjj + v) * SW + c);
#pragma unroll
            for (int u = 0; u < 4; u++)
#pragma unroll
                for (int v = 0; v < 4; v++) {
                    sreg[u][v] = fmaf(qv[u].x, kv[v].x, sreg[u][v]);
                    sreg[u][v] = fmaf(qv[u].y, kv[v].y, sreg[u][v]);
                    sreg[u][v] = fmaf(qv[u].z, kv[v].z, sreg[u][v]);
                    sreg[u][v] = fmaf(qv[u].w, kv[v].w, sreg[u][v]);
                }
        }
#pragma unroll
        for (int u = 0; u < 4; u++)
            *(float4*)(Ss + (sii + u) * SW + sjj) =
                make_float4(sreg[u][0], sreg[u][1], sreg[u][2], sreg[u][3]);
        __syncthreads();

        // online softmax over i, per column jj = t
        if (t < 64) {
            const int jg = j0 + t;
            int ilim = jg - i0 + 1;
            if (ilim > 32) ilim = 32;
            if (ilim < 0) ilim = 0;
            float tmax = -INFINITY;
            for (int ii = 0; ii < ilim; ++ii) tmax = fmaxf(tmax, Ss[ii * SW + t]);
            const float mnew = fmaxf(mcol, tmax);
            const float sc = __expf(mcol - mnew);   // first tile: exp(-inf)=0
            float sum = 0.f;
            for (int ii = 0; ii < ilim; ++ii) {
                const float p = __expf(Ss[ii * SW + t] - mnew);
                Ss[ii * SW + t] = p; sum += p;
            }
            for (int ii = ilim; ii < 32; ++ii) Ss[ii * SW + t] = 0.f;
            lcol = lcol * sc + sum;
            mcol = mnew;
            scl[t] = sc;
        }
        __syncthreads();

        // O[jj][c] = O[jj][c]*scl[jj] + sum_ii P[ii][jj] * V[ii][c]
        const float s0 = scl[tjj], s1 = scl[tjj + 1], s2 = scl[tjj + 2], s3 = scl[tjj + 3];
#pragma unroll
        for (int v = 0; v < 8; v++) {
            acc[0][v] *= s0; acc[1][v] *= s1; acc[2][v] *= s2; acc[3][v] *= s3;
        }
#pragma unroll
        for (int ii = 0; ii < 32; ++ii) {
            const float4 p  = *(const float4*)(Ss + ii * SW + tjj);
            const float4 v0 = *(const float4*)(Vs + ii * SW + tcc);
            const float4 v1 = *(const float4*)(Vs + ii * SW + tcc + 4);
            const float pv[4] = {p.x, p.y, p.z, p.w};
            const float vv[8] = {v0.x, v0.y, v0.z, v0.w, v1.x, v1.y, v1.z, v1.w};
#pragma unroll
            for (int u = 0; u < 4; u++)
#pragma unroll
                for (int v = 0; v < 8; v++) acc[u][v] = fmaf(pv[u], vv[v], acc[u][v]);
        }
    }

    if (t < 64) lb[t] = lcol;
    __syncthreads();
#pragma unroll
    for (int u = 0; u < 4; u++) {
        const float rl = 1.0f / lb[tjj + u];
        float* op = Om + base + ((size_t)(j0 + tjj + u) << 9) + tcc;
        *(float4*)op       = make_float4(acc[u][0] * rl, acc[u][1] * rl, acc[u][2] * rl, acc[u][3] * rl);
        *(float4*)(op + 4) = make_float4(acc[u][4] * rl, acc[u][5] * rl, acc[u][6] * rl, acc[u][7] * rl);
    }
}

// ---------------- kernel 4: LN2 + transpose to (B,D,S) output ---------------
__global__ __launch_bounds__(128) void k_ln2(
    const float* __restrict__ res, const float* __restrict__ g2,
    const float* __restrict__ b2, float* __restrict__ out)
{
    const int bs = blockIdx.x;
    const int b = bs >> 10, s = bs & 1023;
    const int t = threadIdx.x;
    float x[4]; float ls1 = 0.f, ls2 = 0.f;
#pragma unroll
    for (int r = 0; r < 4; r++) {
        x[r] = res[((size_t)bs << 9) + t + (r << 7)];
        ls1 += x[r]; ls2 += x[r] * x[r];
    }
    __shared__ float sa[4], sb[4];
#pragma unroll
    for (int o = 16; o; o >>= 1) {
        ls1 += __shfl_down_sync(0xffffffffu, ls1, o);
        ls2 += __shfl_down_sync(0xffffffffu, ls2, o);
    }
    if ((t & 31) == 0) { sa[t >> 5] = ls1; sb[t >> 5] = ls2; }
    __syncthreads();
    const float S1 = sa[0] + sa[1] + sa[2] + sa[3];
    const float S2 = sb[0] + sb[1] + sb[2] + sb[3];
    const float mean = S1 * (1.0f / 512.0f);
    const float var  = (S2 - 512.0f * mean * mean) * (1.0f / 511.0f);
    const float rstd = rsqrtf(var + 1e-5f);
    const float gg = g2[s], be = b2[s];
#pragma unroll
    for (int r = 0; r < 4; r++) {
        const int d = t + (r << 7);
        out[((size_t)((b << 9) + d) << 10) + s] = gg * (x[r] - mean) * rstd + be;
    }
}

// ---------------- launch ----------------------------------------------------
extern "C" void kernel_launch(void* const* d_in, const int* in_sizes, int n_in,
                              void* d_out, int out_size)
{
    const float* ts     = (const float*)d_in[0];
    const int*   te     = (const int*)  d_in[1];
    const float* conv_w = (const float*)d_in[2];
    const float* conv_b = (const float*)d_in[3];
    const float* pe     = (const float*)d_in[4];
    const float* ts_emb = (const float*)d_in[5];
    const float* g1     = (const float*)d_in[6];
    const float* b1     = (const float*)d_in[7];
    const float* Mw     = (const float*)d_in[8];
    const float* Wq     = (const float*)d_in[9];
    const float* Wk     = (const float*)d_in[10];
    const float* Wv     = (const float*)d_in[11];
    const float* Wo     = (const float*)d_in[12];
    const float* bo     = (const float*)d_in[13];
    const float* g2     = (const float*)d_in[14];
    const float* b2     = (const float*)d_in[15];
    float* out = (float*)d_out;

    float *pc, *pn1, *pd, *pq, *pk, *pv, *pa, *pr;
    cudaGetSymbolAddress((void**)&pc,  g_conv);
    cudaGetSymbolAddress((void**)&pn1, g_n1);
    cudaGetSymbolAddress((void**)&pd,  g_dense);
    cudaGetSymbolAddress((void**)&pq,  g_q);
    cudaGetSymbolAddress((void**)&pk,  g_k);
    cudaGetSymbolAddress((void**)&pv,  g_v);
    cudaGetSymbolAddress((void**)&pa,  g_attn);
    cudaGetSymbolAddress((void**)&pr,  g_res);

    k_embed<<<BSN, 128>>>(ts, conv_w, conv_b, pe, g1, b1, pc, pn1);

    dim3 gg(4, 128);
    sgemm_nt<<<gg, 256>>>(pn1, Mw, pd, 0, te, ts_emb, nullptr);   // dense + ts_emb
    sgemm_nt<<<gg, 256>>>(pd, Wq, pq, 1, nullptr, nullptr, nullptr);  // Q * 1/8
    sgemm_nt<<<gg, 256>>>(pd, Wk, pk, 2, nullptr, nullptr, nullptr);  // K
    sgemm_nt<<<gg, 256>>>(pd, Wv, pv, 2, nullptr, nullptr, nullptr);  // V

    k_attn<<<dim3(SSZ / 64, 8, BB), 128>>>(pq, pk, pv, pa);

    sgemm_nt<<<gg, 256>>>(pa, Wo, pr, 3, nullptr, bo, pc);        // Wo + bo + conv residual

    k_ln2<<<BSN, 128>>>(pr, g2, b2, out);
}

// round 2
// speedup vs baseline: 1.0676x; 1.0676x over previous
#include <cuda_runtime.h>
#include <math.h>

#define BB   16
#define SSZ  1024
#define DDIM 512
#define BSN  (BB*SSZ)   // 16384 rows

// ---------------- scratch (device globals: allocation-free) ----------------
__device__ float g_conv [BB*SSZ*DDIM];
__device__ float g_n1   [BB*SSZ*DDIM];
__device__ float g_dense[BB*SSZ*DDIM];
__device__ float g_q    [BB*SSZ*DDIM];
__device__ float g_k    [BB*SSZ*DDIM];
__device__ float g_v    [BB*SSZ*DDIM];
__device__ float g_attn [BB*SSZ*DDIM];
__device__ float g_res  [BB*SSZ*DDIM];

// ---------------- kernel 1: conv + pe + gelu + LN1 -------------------------
__global__ __launch_bounds__(128) void k_embed(
    const float* __restrict__ ts, const float* __restrict__ cw,
    const float* __restrict__ cb, const float* __restrict__ pe,
    const float* __restrict__ g1, const float* __restrict__ b1,
    float* __restrict__ convo, float* __restrict__ n1o)
{
    const int bs = blockIdx.x;
    const int b = bs >> 10, s = bs & 1023;
    const int t = threadIdx.x;
    const float* tp = ts + ((size_t)b << 12) + (s << 2);
    const float t0 = tp[0], t1 = tp[1], t2 = tp[2], t3 = tp[3];

    float act[4];
    float ls1 = 0.f, ls2 = 0.f;
#pragma unroll
    for (int r = 0; r < 4; r++) {
        const int d = t + (r << 7);
        const float4 w = *(const float4*)(cw + (d << 2));
        float c = fmaf(t0, w.x, fmaf(t1, w.y, fmaf(t2, w.z, t3 * w.w)));
        c += cb[d] + pe[((size_t)s << 9) + d];
        convo[((size_t)bs << 9) + d] = c;
        const float a = 0.5f * c * (1.0f + erff(c * 0.70710678118654752f));
        act[r] = a; ls1 += a; ls2 += a * a;
    }
    __shared__ float sa[4], sb[4];
#pragma unroll
    for (int o = 16; o; o >>= 1) {
        ls1 += __shfl_down_sync(0xffffffffu, ls1, o);
        ls2 += __shfl_down_sync(0xffffffffu, ls2, o);
    }
    if ((t & 31) == 0) { sa[t >> 5] = ls1; sb[t >> 5] = ls2; }
    __syncthreads();
    const float S1 = sa[0] + sa[1] + sa[2] + sa[3];
    const float S2 = sb[0] + sb[1] + sb[2] + sb[3];
    const float mean = S1 * (1.0f / 512.0f);
    const float var  = (S2 - 512.0f * mean * mean) * (1.0f / 511.0f);  // ddof=1
    const float rstd = rsqrtf(var + 1e-5f);
    const float gg = g1[s], be = b1[s];
#pragma unroll
    for (int r = 0; r < 4; r++) {
        const int d = t + (r << 7);
        n1o[((size_t)bs << 9) + d] = gg * (act[r] - mean) * rstd + be;
    }
}

// ---------------- TF32 tensor-core helpers ----------------------------------
__device__ __forceinline__ unsigned f2tf32(float x) {
    unsigned r;
    asm("cvt.rna.tf32.f32 %0, %1;" : "=r"(r) : "f"(x));
    return r;
}
__device__ __forceinline__ void cvt_hl(float x, unsigned& h, unsigned& l) {
    h = f2tf32(x);
    l = f2tf32(x - __uint_as_float(h));
}
__device__ __forceinline__ void mma8(float* c, const unsigned* a, const unsigned* b) {
    asm volatile(
        "mma.sync.aligned.m16n8k8.row.col.f32.tf32.tf32.f32 "
        "{%0,%1,%2,%3}, {%4,%5,%6,%7}, {%8,%9}, {%0,%1,%2,%3};\n"
        : "+f"(c[0]), "+f"(c[1]), "+f"(c[2]), "+f"(c[3])
        : "r"(a[0]), "r"(a[1]), "r"(a[2]), "r"(a[3]), "r"(b[0]), "r"(b[1]));
}

// ---------------- TF32x3 GEMM-NT with fused epilogues ------------------------
// C[m,e] = sum_d A[m,d] * Bw[e,d], M=16384, N=K=512.
// mode 0: += ts_emb[te[b], e]        (B0/C0, aux1=ts_emb, te)
// mode 3: += bo[e] + conv[m,e]       (B0/C0, aux1=bo, aux2=conv)
// mode 4: fused QKV; blockIdx.z in {0,1,2} picks (B0,C0)=Q(*0.125),(B1,C1)=K,(B2,C2)=V
#define SP 9   // smem row stride (8 + 1 pad, conflict-free fragment loads)
__global__ __launch_bounds__(256) void tf32_gemm(
    const float* __restrict__ A,
    const float* __restrict__ B0, const float* __restrict__ B1, const float* __restrict__ B2,
    float* __restrict__ C0, float* __restrict__ C1, float* __restrict__ C2,
    int mode, const int* __restrict__ te,
    const float* __restrict__ aux1, const float* __restrict__ aux2)
{
    __shared__ unsigned Ah[128 * SP], Al[128 * SP], Bh[128 * SP], Bl[128 * SP];

    const float* Bw = B0;
    float* C = C0;
    float scale = 1.0f;
    if (mode == 4) {
        if (blockIdx.z == 0)      { scale = 0.125f; }
        else if (blockIdx.z == 1) { Bw = B1; C = C1; }
        else                      { Bw = B2; C = C2; }
    }

    const int t = threadIdx.x;
    const int row0 = blockIdx.y << 7, col0 = blockIdx.x << 7;

    // loader mapping: 256 threads, each loads one float4 per matrix per k8
    const int lr = t >> 1, lc = (t & 1) << 2;
    const float* Ag = A  + ((size_t)(row0 + lr) << 9) + lc;
    const float* Bg = Bw + ((size_t)(col0 + lr) << 9) + lc;

    // warp tiling: 8 warps -> 2 (m) x 4 (n); warp tile 64x32
    const int warp = t >> 5, lane = t & 31;
    const int gid = lane >> 2, tig = lane & 3;
    const int wm = warp & 1, wn = warp >> 1;

    float acc[4][4][4];
#pragma unroll
    for (int mt = 0; mt < 4; mt++)
#pragma unroll
        for (int nt = 0; nt < 4; nt++)
#pragma unroll
            for (int r = 0; r < 4; r++) acc[mt][nt][r] = 0.f;

    float4 av = *(const float4*)Ag;
    float4 bv = *(const float4*)Bg;

    for (int k0 = 0; k0 < 512; k0 += 8) {
        __syncthreads();
        {
            unsigned h, l;
            const int sa = lr * SP + lc;
            cvt_hl(av.x, h, l); Ah[sa    ] = h; Al[sa    ] = l;
            cvt_hl(av.y, h, l); Ah[sa + 1] = h; Al[sa + 1] = l;
            cvt_hl(av.z, h, l); Ah[sa + 2] = h; Al[sa + 2] = l;
            cvt_hl(av.w, h, l); Ah[sa + 3] = h; Al[sa + 3] = l;
            cvt_hl(bv.x, h, l); Bh[sa    ] = h; Bl[sa    ] = l;
            cvt_hl(bv.y, h, l); Bh[sa + 1] = h; Bl[sa + 1] = l;
            cvt_hl(bv.z, h, l); Bh[sa + 2] = h; Bl[sa + 2] = l;
            cvt_hl(bv.w, h, l); Bh[sa + 3] = h; Bl[sa + 3] = l;
        }
        __syncthreads();
        if (k0 < 504) {
            av = *(const float4*)(Ag + k0 + 8);
            bv = *(const float4*)(Bg + k0 + 8);
        }

        unsigned bh[4][2], bl[4][2];
#pragma unroll
        for (int nt = 0; nt < 4; nt++) {
            const int r = ((wn << 5) + (nt << 3) + gid) * SP;
            bh[nt][0] = Bh[r + tig]; bh[nt][1] = Bh[r + tig + 4];
            bl[nt][0] = Bl[r + tig]; bl[nt][1] = Bl[r + tig + 4];
        }
#pragma unroll
        for (int mt = 0; mt < 4; mt++) {
            const int r  = ((wm << 6) + (mt << 4) + gid) * SP;
            const int r8 = r + 8 * SP;
            unsigned ah[4] = {Ah[r + tig], Ah[r8 + tig], Ah[r + tig + 4], Ah[r8 + tig + 4]};
            unsigned al[4] = {Al[r + tig], Al[r8 + tig], Al[r + tig + 4], Al[r8 + tig + 4]};
#pragma unroll
            for (int nt = 0; nt < 4; nt++) {
                mma8(acc[mt][nt], al, bh[nt]);   // lo*hi
                mma8(acc[mt][nt], ah, bl[nt]);   // hi*lo
                mma8(acc[mt][nt], ah, bh[nt]);   // hi*hi
            }
        }
    }

    // ---- epilogue ----
    int e = 0;
    if (mode == 0) e = te[row0 >> 10];

#pragma unroll
    for (int mt = 0; mt < 4; mt++) {
        const int r1 = row0 + (wm << 6) + (mt << 4) + gid;
        const int r2 = r1 + 8;
#pragma unroll
        for (int nt = 0; nt < 4; nt++) {
            const int c = col0 + (wn << 5) + (nt << 3) + (tig << 1);
            float add0 = 0.f, add1 = 0.f;
            if (mode == 0) {
                add0 = aux1[((size_t)e << 9) + c];
                add1 = aux1[((size_t)e << 9) + c + 1];
            } else if (mode == 3) {
                add0 = aux1[c]; add1 = aux1[c + 1];
            }
            float v0 = acc[mt][nt][0] * scale + add0;
            float v1 = acc[mt][nt][1] * scale + add1;
            float v2 = acc[mt][nt][2] * scale + add0;
            float v3 = acc[mt][nt][3] * scale + add1;
            if (mode == 3) {
                v0 += aux2[((size_t)r1 << 9) + c];
                v1 += aux2[((size_t)r1 << 9) + c + 1];
                v2 += aux2[((size_t)r2 << 9) + c];
                v3 += aux2[((size_t)r2 << 9) + c + 1];
            }
            *(float2*)(C + ((size_t)r1 << 9) + c) = make_float2(v0, v1);
            *(float2*)(C + ((size_t)r2 << 9) + c) = make_float2(v2, v3);
        }
    }
}

// ---------------- kernel 3: "transposed" causal flash attention -------------
#define SW 68
__global__ __launch_bounds__(128) void k_attn(
    const float* __restrict__ Qm, const float* __restrict__ Km,
    const float* __restrict__ Vm, float* __restrict__ Om)
{
    __shared__ __align__(16) float Ks[64 * SW];
    __shared__ __align__(16) float Qs[32 * SW];
    __shared__ __align__(16) float Vs[32 * SW];
    __shared__ __align__(16) float Ss[32 * SW];
    __shared__ float scl[64];
    __shared__ float lb[64];

    const int jt = blockIdx.x, h = blockIdx.y, b = blockIdx.z;
    const int j0 = jt << 6;
    const int t = threadIdx.x;
    const size_t base = ((size_t)b << 19) + (h << 6);
    const int r0 = t >> 4, c4 = (t & 15) << 2;

#pragma unroll
    for (int rr = 0; rr < 8; rr++) {
        const int r = r0 + (rr << 3);
        *(float4*)(Ks + r * SW + c4) =
            *(const float4*)(Km + base + ((size_t)(j0 + r) << 9) + c4);
    }

    float mcol = -INFINITY, lcol = 0.f;
    float acc[4][8];
#pragma unroll
    for (int u = 0; u < 4; u++)
#pragma unroll
        for (int v = 0; v < 8; v++) acc[u][v] = 0.f;

    const int tjj = (t & 15) << 2, tcc = (t >> 4) << 3;
    const int sii = (t >> 4) << 2, sjj = (t & 15) << 2;
    const int ntiles = (jt << 1) + 2;

    for (int it = 0; it < ntiles; ++it) {
        const int i0 = it << 5;
        __syncthreads();
#pragma unroll
        for (int rr = 0; rr < 4; rr++) {
            const int r = r0 + (rr << 3);
            *(float4*)(Qs + r * SW + c4) =
                *(const float4*)(Qm + base + ((size_t)(i0 + r) << 9) + c4);
            *(float4*)(Vs + r * SW + c4) =
                *(const float4*)(Vm + base + ((size_t)(i0 + r) << 9) + c4);
        }
        __syncthreads();

        float sreg[4][4];
#pragma unroll
        for (int u = 0; u < 4; u++)
#pragma unroll
            for (int v = 0; v < 4; v++) sreg[u][v] = 0.f;
#pragma unroll
        for (int c = 0; c < 64; c += 4) {
            float4 qv[4], kv[4];
#pragma unroll
            for (int u = 0; u < 4; u++) qv[u] = *(const float4*)(Qs + (sii + u) * SW + c);
#pragma unroll
            for (int v = 0; v < 4; v++) kv[v] = *(const float4*)(Ks + (sjj + v) * SW + c);
#pragma unroll
            for (int u = 0; u < 4; u++)
#pragma unroll
                for (int v = 0; v < 4; v++) {
                    sreg[u][v] = fmaf(qv[u].x, kv[v].x, sreg[u][v]);
                    sreg[u][v] = fmaf(qv[u].y, kv[v].y, sreg[u][v]);
                    sreg[u][v] = fmaf(qv[u].z, kv[v].z, sreg[u][v]);
                    sreg[u][v] = fmaf(qv[u].w, kv[v].w, sreg[u][v]);
                }
        }
#pragma unroll
        for (int u = 0; u < 4; u++)
            *(float4*)(Ss + (sii + u) * SW + sjj) =
                make_float4(sreg[u][0], sreg[u][1], sreg[u][2], sreg[u][3]);
        __syncthreads();

        if (t < 64) {
            const int jg = j0 + t;
            int ilim = jg - i0 + 1;
            if (ilim > 32) ilim = 32;
            if (ilim < 0) ilim = 0;
            float tmax = -INFINITY;
            for (int ii = 0; ii < ilim; ++ii) tmax = fmaxf(tmax, Ss[ii * SW + t]);
            const float mnew = fmaxf(mcol, tmax);
            const float sc = __expf(mcol - mnew);
            float sum = 0.f;
            for (int ii = 0; ii < ilim; ++ii) {
                const float p = __expf(Ss[ii * SW + t] - mnew);
                Ss[ii * SW + t] = p; sum += p;
            }
            for (int ii = ilim; ii < 32; ++ii) Ss[ii * SW + t] = 0.f;
            lcol = lcol * sc + sum;
            mcol = mnew;
            scl[t] = sc;
        }
        __syncthreads();

        const float s0 = scl[tjj], s1 = scl[tjj + 1], s2 = scl[tjj + 2], s3 = scl[tjj + 3];
#pragma unroll
        for (int v = 0; v < 8; v++) {
            acc[0][v] *= s0; acc[1][v] *= s1; acc[2][v] *= s2; acc[3][v] *= s3;
        }
#pragma unroll
        for (int ii = 0; ii < 32; ++ii) {
            const float4 p  = *(const float4*)(Ss + ii * SW + tjj);
            const float4 v0 = *(const float4*)(Vs + ii * SW + tcc);
            const float4 v1 = *(const float4*)(Vs + ii * SW + tcc + 4);
            const float pv[4] = {p.x, p.y, p.z, p.w};
            const float vv[8] = {v0.x, v0.y, v0.z, v0.w, v1.x, v1.y, v1.z, v1.w};
#pragma unroll
            for (int u = 0; u < 4; u++)
#pragma unroll
                for (int v = 0; v < 8; v++) acc[u][v] = fmaf(pv[u], vv[v], acc[u][v]);
        }
    }

    if (t < 64) lb[t] = lcol;
    __syncthreads();
#pragma unroll
    for (int u = 0; u < 4; u++) {
        const float rl = 1.0f / lb[tjj + u];
        float* op = Om + base + ((size_t)(j0 + tjj + u) << 9) + tcc;
        *(float4*)op       = make_float4(acc[u][0] * rl, acc[u][1] * rl, acc[u][2] * rl, acc[u][3] * rl);
        *(float4*)(op + 4) = make_float4(acc[u][4] * rl, acc[u][5] * rl, acc[u][6] * rl, acc[u][7] * rl);
    }
}

// ---------------- kernel 4: LN2 + transpose to (B,D,S) output ---------------
__global__ __launch_bounds__(128) void k_ln2(
    const float* __restrict__ res, const float* __restrict__ g2,
    const float* __restrict__ b2, float* __restrict__ out)
{
    const int bs = blockIdx.x;
    const int b = bs >> 10, s = bs & 1023;
    const int t = threadIdx.x;
    float x[4]; float ls1 = 0.f, ls2 = 0.f;
#pragma unroll
    for (int r = 0; r < 4; r++) {
        x[r] = res[((size_t)bs << 9) + t + (r << 7)];
        ls1 += x[r]; ls2 += x[r] * x[r];
    }
    __shared__ float sa[4], sb[4];
#pragma unroll
    for (int o = 16; o; o >>= 1) {
        ls1 += __shfl_down_sync(0xffffffffu, ls1, o);
        ls2 += __shfl_down_sync(0xffffffffu, ls2, o);
    }
    if ((t & 31) == 0) { sa[t >> 5] = ls1; sb[t >> 5] = ls2; }
    __syncthreads();
    const float S1 = sa[0] + sa[1] + sa[2] + sa[3];
    const float S2 = sb[0] + sb[1] + sb[2] + sb[3];
    const float mean = S1 * (1.0f / 512.0f);
    const float var  = (S2 - 512.0f * mean * mean) * (1.0f / 511.0f);
    const float rstd = rsqrtf(var + 1e-5f);
    const float gg = g2[s], be = b2[s];
#pragma unroll
    for (int r = 0; r < 4; r++) {
        const int d = t + (r << 7);
        out[((size_t)((b << 9) + d) << 10) + s] = gg * (x[r] - mean) * rstd + be;
    }
}

// ---------------- launch ----------------------------------------------------
extern "C" void kernel_launch(void* const* d_in, const int* in_sizes, int n_in,
                              void* d_out, int out_size)
{
    const float* ts     = (const float*)d_in[0];
    const int*   te     = (const int*)  d_in[1];
    const float* conv_w = (const float*)d_in[2];
    const float* conv_b = (const float*)d_in[3];
    const float* pe     = (const float*)d_in[4];
    const float* ts_emb = (const float*)d_in[5];
    const float* g1     = (const float*)d_in[6];
    const float* b1     = (const float*)d_in[7];
    const float* Mw     = (const float*)d_in[8];
    const float* Wq     = (const float*)d_in[9];
    const float* Wk     = (const float*)d_in[10];
    const float* Wv     = (const float*)d_in[11];
    const float* Wo     = (const float*)d_in[12];
    const float* bo     = (const float*)d_in[13];
    const float* g2     = (const float*)d_in[14];
    const float* b2     = (const float*)d_in[15];
    float* out = (float*)d_out;

    float *pc, *pn1, *pd, *pq, *pk, *pv, *pa, *pr;
    cudaGetSymbolAddress((void**)&pc,  g_conv);
    cudaGetSymbolAddress((void**)&pn1, g_n1);
    cudaGetSymbolAddress((void**)&pd,  g_dense);
    cudaGetSymbolAddress((void**)&pq,  g_q);
    cudaGetSymbolAddress((void**)&pk,  g_k);
    cudaGetSymbolAddress((void**)&pv,  g_v);
    cudaGetSymbolAddress((void**)&pa,  g_attn);
    cudaGetSymbolAddress((void**)&pr,  g_res);

    k_embed<<<BSN, 128>>>(ts, conv_w, conv_b, pe, g1, b1, pc, pn1);

    dim3 gg(4, 128, 1);
    // dense = M @ n1 + ts_emb gather
    tf32_gemm<<<gg, 256>>>(pn1, Mw, nullptr, nullptr, pd, nullptr, nullptr,
                           0, te, ts_emb, nullptr);
    // fused QKV (z=0: Q*0.125, z=1: K, z=2: V)
    dim3 gq(4, 128, 3);
    tf32_gemm<<<gq, 256>>>(pd, Wq, Wk, Wv, pq, pk, pv,
                           4, nullptr, nullptr, nullptr);

    k_attn<<<dim3(SSZ / 64, 8, BB), 128>>>(pq, pk, pv, pa);

    // out = Wo @ attn + bo + conv residual
    tf32_gemm<<<gg, 256>>>(pa, Wo, nullptr, nullptr, pr, nullptr, nullptr,
                           3, nullptr, bo, pc);

    k_ln2<<<BSN, 128>>>(pr, g2, b2, out);
}

// round 4
// speedup vs baseline: 1.2446x; 1.1659x over previous
#include <cuda_runtime.h>
#include <math.h>

#define BB   16
#define SSZ  1024
#define DDIM 512
#define BSN  (BB*SSZ)   // 16384 rows
#define NEGF (-1e30f)

// ---------------- scratch (device globals: allocation-free) ----------------
__device__ float    g_conv [BSN*DDIM];
__device__ float    g_res  [BSN*DDIM];
__device__ unsigned g_n1h[BSN*DDIM], g_n1l[BSN*DDIM];
__device__ unsigned g_dh [BSN*DDIM], g_dl [BSN*DDIM];
__device__ unsigned g_qh [BSN*DDIM], g_ql [BSN*DDIM];
__device__ unsigned g_kh [BSN*DDIM], g_kl [BSN*DDIM];
__device__ unsigned g_vh [BSN*DDIM], g_vl [BSN*DDIM];
__device__ unsigned g_ah [BSN*DDIM], g_al [BSN*DDIM];
__device__ unsigned g_wmh[DDIM*DDIM], g_wml[DDIM*DDIM];
__device__ unsigned g_wqh[DDIM*DDIM], g_wql[DDIM*DDIM];
__device__ unsigned g_wkh[DDIM*DDIM], g_wkl[DDIM*DDIM];
__device__ unsigned g_wvh[DDIM*DDIM], g_wvl[DDIM*DDIM];
__device__ unsigned g_woh[DDIM*DDIM], g_wol[DDIM*DDIM];

// ---------------- helpers ----------------------------------------------------
__device__ __forceinline__ unsigned f2tf32(float x) {
    unsigned r;
    asm("cvt.rna.tf32.f32 %0, %1;" : "=r"(r) : "f"(x));
    return r;
}
__device__ __forceinline__ void cvt_hl(float x, unsigned& h, unsigned& l) {
    h = f2tf32(x);
    l = f2tf32(x - __uint_as_float(h));
}
__device__ __forceinline__ void mma8(float* c, const unsigned* a, const unsigned* b) {
    asm volatile(
        "mma.sync.aligned.m16n8k8.row.col.f32.tf32.tf32.f32 "
        "{%0,%1,%2,%3}, {%4,%5,%6,%7}, {%8,%9}, {%0,%1,%2,%3};\n"
        : "+f"(c[0]), "+f"(c[1]), "+f"(c[2]), "+f"(c[3])
        : "r"(a[0]), "r"(a[1]), "r"(a[2]), "r"(a[3]), "r"(b[0]), "r"(b[1]));
}
__device__ __forceinline__ unsigned su32(const void* p) {
    return (unsigned)__cvta_generic_to_shared(p);
}
#define CP16(d, s) asm volatile("cp.async.cg.shared.global [%0], [%1], 16;\n" :: "r"(d), "l"(s))
#define CP_COMMIT()  asm volatile("cp.async.commit_group;\n")
#define CP_WAIT1()   asm volatile("cp.async.wait_group 1;\n")

// ---------------- kernel: fp32 -> (hi, lo) tf32 split for 5 weights ----------
struct CvtTab { const float4* in[5]; uint4* oh[5]; uint4* ol[5]; };
__global__ __launch_bounds__(256) void k_cvt5(CvtTab tab, int n4)
{
    const int w = blockIdx.y;
    int i = blockIdx.x * 256 + threadIdx.x;
    if (i >= n4) return;
    float4 v = tab.in[w][i];
    uint4 H, L;
    cvt_hl(v.x, H.x, L.x); cvt_hl(v.y, H.y, L.y);
    cvt_hl(v.z, H.z, L.z); cvt_hl(v.w, H.w, L.w);
    tab.oh[w][i] = H; tab.ol[w][i] = L;
}

// ---------------- kernel 1: conv + pe + gelu + LN1 (emits hi/lo) -------------
__global__ __launch_bounds__(128) void k_embed(
    const float* __restrict__ ts, const float* __restrict__ cw,
    const float* __restrict__ cb, const float* __restrict__ pe,
    const float* __restrict__ g1, const float* __restrict__ b1,
    float* __restrict__ convo, unsigned* __restrict__ n1h, unsigned* __restrict__ n1l)
{
    const int bs = blockIdx.x;
    const int b = bs >> 10, s = bs & 1023;
    const int t = threadIdx.x;
    const float* tp = ts + ((size_t)b << 12) + (s << 2);
    const float t0 = tp[0], t1 = tp[1], t2 = tp[2], t3 = tp[3];

    float act[4];
    float ls1 = 0.f, ls2 = 0.f;
#pragma unroll
    for (int r = 0; r < 4; r++) {
        const int d = t + (r << 7);
        const float4 w = *(const float4*)(cw + (d << 2));
        float c = fmaf(t0, w.x, fmaf(t1, w.y, fmaf(t2, w.z, t3 * w.w)));
        c += cb[d] + pe[((size_t)s << 9) + d];
        convo[((size_t)bs << 9) + d] = c;
        const float a = 0.5f * c * (1.0f + erff(c * 0.70710678118654752f));
        act[r] = a; ls1 += a; ls2 += a * a;
    }
    __shared__ float sa[4], sb[4];
#pragma unroll
    for (int o = 16; o; o >>= 1) {
        ls1 += __shfl_down_sync(0xffffffffu, ls1, o);
        ls2 += __shfl_down_sync(0xffffffffu, ls2, o);
    }
    if ((t & 31) == 0) { sa[t >> 5] = ls1; sb[t >> 5] = ls2; }
    __syncthreads();
    const float S1 = sa[0] + sa[1] + sa[2] + sa[3];
    const float S2 = sb[0] + sb[1] + sb[2] + sb[3];
    const float mean = S1 * (1.0f / 512.0f);
    const float var  = (S2 - 512.0f * mean * mean) * (1.0f / 511.0f);  // ddof=1
    const float rstd = rsqrtf(var + 1e-5f);
    const float gg = g1[s], be = b1[s];
#pragma unroll
    for (int r = 0; r < 4; r++) {
        const int d = t + (r << 7);
        const float v = gg * (act[r] - mean) * rstd + be;
        unsigned h, l; cvt_hl(v, h, l);
        n1h[((size_t)bs << 9) + d] = h;
        n1l[((size_t)bs << 9) + d] = l;
    }
}

// ---------------- TF32x3 GEMM-NT, precomputed hi/lo operands -----------------
#define GSP 20
#define GSTG 10240   // uints per stage (4 arrays x 128*20)
__global__ __launch_bounds__(256, 2) void tf32_gemm2(
    const unsigned* __restrict__ Agh, const unsigned* __restrict__ Agl,
    const unsigned* __restrict__ B0h, const unsigned* __restrict__ B0l,
    const unsigned* __restrict__ B1h, const unsigned* __restrict__ B1l,
    const unsigned* __restrict__ B2h, const unsigned* __restrict__ B2l,
    unsigned* __restrict__ C0h, unsigned* __restrict__ C0l,
    unsigned* __restrict__ C1h, unsigned* __restrict__ C1l,
    unsigned* __restrict__ C2h, unsigned* __restrict__ C2l,
    float* __restrict__ Cf, int mode, const int* __restrict__ te,
    const float* __restrict__ aux1, const float* __restrict__ aux2)
{
    extern __shared__ unsigned gsm[];

    const unsigned* Bgh = B0h; const unsigned* Bgl = B0l;
    unsigned* Ch = C0h; unsigned* Cl = C0l;
    float scale = 1.0f;
    if (mode == 4) {
        if (blockIdx.z == 1)      { Bgh = B1h; Bgl = B1l; Ch = C1h; Cl = C1l; }
        else if (blockIdx.z == 2) { Bgh = B2h; Bgl = B2l; Ch = C2h; Cl = C2l; }
        else                      { scale = 0.125f; }
    }

    const int t = threadIdx.x;
    const int row0 = blockIdx.y << 7, col0 = blockIdx.x << 7;
    const int lrow = t >> 1, lhalf = (t & 1) << 3;
    const size_t aoff = ((size_t)(row0 + lrow) << 9) + lhalf;
    const size_t boff = ((size_t)(col0 + lrow) << 9) + lhalf;
    const unsigned sdst0 = su32(gsm) + (unsigned)((lrow * GSP + lhalf) << 2);

    const int warp = t >> 5, lane = t & 31;
    const int gid = lane >> 2, tig = lane & 3;
    const int wm = warp & 1, wn = warp >> 1;

    float acc[4][4][4];
#pragma unroll
    for (int mt = 0; mt < 4; mt++)
#pragma unroll
        for (int nt = 0; nt < 4; nt++)
#pragma unroll
            for (int r = 0; r < 4; r++) acc[mt][nt][r] = 0.f;

#define GLOAD(kt, st) do {                                              \
        const unsigned kc = (unsigned)(kt) << 4;                        \
        const unsigned sd = sdst0 + (st) * (GSTG << 2);                 \
        CP16(sd,                     Agh + aoff + kc);                  \
        CP16(sd + 16,                Agh + aoff + kc + 4);              \
        CP16(sd + (2560u<<2),        Agl + aoff + kc);                  \
        CP16(sd + (2560u<<2) + 16,   Agl + aoff + kc + 4);              \
        CP16(sd + (5120u<<2),        Bgh + boff + kc);                  \
        CP16(sd + (5120u<<2) + 16,   Bgh + boff + kc + 4);              \
        CP16(sd + (7680u<<2),        Bgl + boff + kc);                  \
        CP16(sd + (7680u<<2) + 16,   Bgl + boff + kc + 4);              \
    } while (0)

    GLOAD(0, 0); CP_COMMIT();
    GLOAD(1, 1); CP_COMMIT();

    for (int kt = 0; kt < 32; kt++) {
        CP_WAIT1();
        __syncthreads();
        const unsigned* S   = gsm + (kt & 1) * GSTG;
        const unsigned* SAh = S;
        const unsigned* SAl = S + 2560;
        const unsigned* SBh = S + 5120;
        const unsigned* SBl = S + 7680;
#pragma unroll
        for (int ks = 0; ks < 2; ks++) {
            const int kb = (ks << 3) + tig;
            unsigned bh[4][2], bl[4][2];
#pragma unroll
            for (int nt = 0; nt < 4; nt++) {
                const int rr = ((wn << 5) + (nt << 3) + gid) * GSP + kb;
                bh[nt][0] = SBh[rr]; bh[nt][1] = SBh[rr + 4];
                bl[nt][0] = SBl[rr]; bl[nt][1] = SBl[rr + 4];
            }
#pragma unroll
            for (int mt = 0; mt < 4; mt++) {
                const int r0 = ((wm << 6) + (mt << 4) + gid) * GSP + kb;
                const int r8 = r0 + 8 * GSP;
                unsigned ah[4] = {SAh[r0], SAh[r8], SAh[r0 + 4], SAh[r8 + 4]};
                unsigned al[4] = {SAl[r0], SAl[r8], SAl[r0 + 4], SAl[r8 + 4]};
#pragma unroll
                for (int nt = 0; nt < 4; nt++) {
                    mma8(acc[mt][nt], al, bh[nt]);
                    mma8(acc[mt][nt], ah, bl[nt]);
                    mma8(acc[mt][nt], ah, bh[nt]);
                }
            }
        }
        __syncthreads();
        if (kt + 2 < 32) GLOAD(kt + 2, kt & 1);
        CP_COMMIT();
    }

    if (mode == 3) {
#pragma unroll
        for (int mt = 0; mt < 4; mt++) {
            const int r1 = row0 + (wm << 6) + (mt << 4) + gid;
            const int r2 = r1 + 8;
#pragma unroll
            for (int nt = 0; nt < 4; nt++) {
                const int c = col0 + (wn << 5) + (nt << 3) + (tig << 1);
                const float a0 = aux1[c], a1 = aux1[c + 1];
                float v0 = acc[mt][nt][0] + a0 + aux2[((size_t)r1 << 9) + c];
                float v1 = acc[mt][nt][1] + a1 + aux2[((size_t)r1 << 9) + c + 1];
                float v2 = acc[mt][nt][2] + a0 + aux2[((size_t)r2 << 9) + c];
                float v3 = acc[mt][nt][3] + a1 + aux2[((size_t)r2 << 9) + c + 1];
                *(float2*)(Cf + ((size_t)r1 << 9) + c) = make_float2(v0, v1);
                *(float2*)(Cf + ((size_t)r2 << 9) + c) = make_float2(v2, v3);
            }
        }
    } else {
        int e = 0;
        if (mode == 0) e = te[row0 >> 10];
#pragma unroll
        for (int mt = 0; mt < 4; mt++) {
            const int r1 = row0 + (wm << 6) + (mt << 4) + gid;
            const int r2 = r1 + 8;
#pragma unroll
            for (int nt = 0; nt < 4; nt++) {
                const int c = col0 + (wn << 5) + (nt << 3) + (tig << 1);
                float a0 = 0.f, a1 = 0.f;
                if (mode == 0) {
                    a0 = aux1[((size_t)e << 9) + c];
                    a1 = aux1[((size_t)e << 9) + c + 1];
                }
                float v[4];
                v[0] = acc[mt][nt][0] * scale + a0;
                v[1] = acc[mt][nt][1] * scale + a1;
                v[2] = acc[mt][nt][2] * scale + a0;
                v[3] = acc[mt][nt][3] * scale + a1;
                const size_t i00 = ((size_t)r1 << 9) + c;
                const size_t i10 = ((size_t)r2 << 9) + c;
                unsigned h, l;
                cvt_hl(v[0], h, l); Ch[i00]     = h; Cl[i00]     = l;
                cvt_hl(v[1], h, l); Ch[i00 + 1] = h; Cl[i00 + 1] = l;
                cvt_hl(v[2], h, l); Ch[i10]     = h; Cl[i10]     = l;
                cvt_hl(v[3], h, l); Ch[i10 + 1] = h; Cl[i10 + 1] = l;
            }
        }
    }
}

// ---------------- tensor-core "transposed" causal flash attention ------------
#define A_KSH 0
#define A_KSL (64*68)
#define A_QSH (2*64*68)
#define A_QSL (A_QSH + 32*68)
#define A_VTH (A_QSL + 32*68)
#define A_VTL (A_VTH + 64*36)
#define A_PSH (A_VTL + 64*36)
#define A_PSL (A_PSH + 64*36)
#define A_TOT (A_PSL + 64*36)     // 22272 uints = 89088 B
__global__ __launch_bounds__(128, 2) void k_attn2(
    const unsigned* __restrict__ qh, const unsigned* __restrict__ ql,
    const unsigned* __restrict__ kh, const unsigned* __restrict__ kl,
    const unsigned* __restrict__ vh, const unsigned* __restrict__ vl,
    unsigned* __restrict__ aoh, unsigned* __restrict__ aol)
{
    extern __shared__ unsigned sm[];
    unsigned* KSH = sm + A_KSH; unsigned* KSL = sm + A_KSL;
    unsigned* QSH = sm + A_QSH; unsigned* QSL = sm + A_QSL;
    unsigned* VTH = sm + A_VTH; unsigned* VTL = sm + A_VTL;
    unsigned* PSH = sm + A_PSH; unsigned* PSL = sm + A_PSL;

    const int jt = (gridDim.x - 1) - blockIdx.x;
    const int h = blockIdx.y, b = blockIdx.z;
    const int j0 = jt << 6;
    const int t = threadIdx.x, warp = t >> 5, lane = t & 31;
    const int gid = lane >> 2, tig = lane & 3;
    const size_t rowb = ((size_t)b << 10);
    const int coff = h << 6;

    {
        const int arr = t >> 6, r = t & 63;
        const unsigned* g = arr ? kl : kh;
        const uint4* gs = (const uint4*)(g + ((rowb + j0 + r) << 9) + coff);
        unsigned* d = (arr ? KSL : KSH) + r * 68;
#pragma unroll
        for (int i = 0; i < 16; i++) *(uint4*)(d + (i << 2)) = gs[i];
    }

    float m0 = NEGF, m1 = NEGF, l0 = 0.f, l1 = 0.f;
    float acc[8][4];
#pragma unroll
    for (int nb = 0; nb < 8; nb++)
#pragma unroll
        for (int r = 0; r < 4; r++) acc[nb][r] = 0.f;

    const int ntiles = (jt << 1) + 2;
    const int jr0 = j0 + (warp << 4) + gid, jr1 = jr0 + 8;

    for (int it = 0; it < ntiles; ++it) {
        const int i0 = it << 5;
        __syncthreads();
        {
            const int arr = t >> 6, r = (t & 63) >> 1, half = t & 1;
            const unsigned* gq = arr ? ql : qh;
            const uint4* gs = (const uint4*)(gq + ((rowb + i0 + r) << 9) + coff) + (half << 3);
            unsigned* d = (arr ? QSL : QSH) + r * 68 + (half << 5);
#pragma unroll
            for (int i = 0; i < 8; i++) *(uint4*)(d + (i << 2)) = gs[i];

            const unsigned* gv = arr ? vl : vh;
            const uint4* vs = (const uint4*)(gv + ((rowb + i0 + r) << 9) + coff) + (half << 3);
            unsigned* dv = arr ? VTL : VTH;
#pragma unroll
            for (int i = 0; i < 8; i++) {
                uint4 x = vs[i];
                const int c = (half << 5) + (i << 2);
                dv[ c      * 36 + r] = x.x;
                dv[(c + 1) * 36 + r] = x.y;
                dv[(c + 2) * 36 + r] = x.z;
                dv[(c + 3) * 36 + r] = x.w;
            }
        }
        __syncthreads();

        float s[4][4];
#pragma unroll
        for (int nb = 0; nb < 4; nb++)
#pragma unroll
            for (int r = 0; r < 4; r++) s[nb][r] = 0.f;
#pragma unroll
        for (int ks = 0; ks < 8; ks++) {
            const int kb = (ks << 3) + tig;
            const int r0 = ((warp << 4) + gid) * 68 + kb;
            const int r8 = r0 + 8 * 68;
            unsigned ah[4] = {KSH[r0], KSH[r8], KSH[r0 + 4], KSH[r8 + 4]};
            unsigned al[4] = {KSL[r0], KSL[r8], KSL[r0 + 4], KSL[r8 + 4]};
#pragma unroll
            for (int nb = 0; nb < 4; nb++) {
                const int rr = ((nb << 3) + gid) * 68 + kb;
                unsigned bh[2] = {QSH[rr], QSH[rr + 4]};
                unsigned bl[2] = {QSL[rr], QSL[rr + 4]};
                mma8(s[nb], al, bh);
                mma8(s[nb], ah, bl);
                mma8(s[nb], ah, bh);
            }
        }

        if (it >= ntiles - 2) {
#pragma unroll
            for (int nb = 0; nb < 4; nb++) {
                const int c = i0 + (nb << 3) + (tig << 1);
                if (c     > jr0) s[nb][0] = NEGF;
                if (c + 1 > jr0) s[nb][1] = NEGF;
                if (c     > jr1) s[nb][2] = NEGF;
                if (c + 1 > jr1) s[nb][3] = NEGF;
            }
        }

        float mt0 = NEGF, mt1 = NEGF;
#pragma unroll
        for (int nb = 0; nb < 4; nb++) {
            mt0 = fmaxf(mt0, fmaxf(s[nb][0], s[nb][1]));
            mt1 = fmaxf(mt1, fmaxf(s[nb][2], s[nb][3]));
        }
        mt0 = fmaxf(mt0, __shfl_xor_sync(0xffffffffu, mt0, 1));
        mt0 = fmaxf(mt0, __shfl_xor_sync(0xffffffffu, mt0, 2));
        mt1 = fmaxf(mt1, __shfl_xor_sync(0xffffffffu, mt1, 1));
        mt1 = fmaxf(mt1, __shfl_xor_sync(0xffffffffu, mt1, 2));
        const float mn0 = fmaxf(m0, mt0), mn1 = fmaxf(m1, mt1);
        const float sc0 = __expf(m0 - mn0), sc1 = __expf(m1 - mn1);
        m0 = mn0; m1 = mn1;

        float rs0 = 0.f, rs1 = 0.f;
        const int prA = (warp << 4) + gid, prB = prA + 8;
#pragma unroll
        for (int nb = 0; nb < 4; nb++) {
            const int c0 = (nb << 3) + (tig << 1);
            unsigned hh, ll;
            s[nb][0] = __expf(s[nb][0] - mn0);
            s[nb][1] = __expf(s[nb][1] - mn0);
            s[nb][2] = __expf(s[nb][2] - mn1);
            s[nb][3] = __expf(s[nb][3] - mn1);
            rs0 += s[nb][0] + s[nb][1];
            rs1 += s[nb][2] + s[nb][3];
            cvt_hl(s[nb][0], hh, ll); PSH[prA * 36 + c0]     = hh; PSL[prA * 36 + c0]     = ll;
            cvt_hl(s[nb][1], hh, ll); PSH[prA * 36 + c0 + 1] = hh; PSL[prA * 36 + c0 + 1] = ll;
            cvt_hl(s[nb][2], hh, ll); PSH[prB * 36 + c0]     = hh; PSL[prB * 36 + c0]     = ll;
            cvt_hl(s[nb][3], hh, ll); PSH[prB * 36 + c0 + 1] = hh; PSL[prB * 36 + c0 + 1] = ll;
        }
        rs0 += __shfl_xor_sync(0xffffffffu, rs0, 1);
        rs0 += __shfl_xor_sync(0xffffffffu, rs0, 2);
        rs1 += __shfl_xor_sync(0xffffffffu, rs1, 1);
        rs1 += __shfl_xor_sync(0xffffffffu, rs1, 2);
        l0 = l0 * sc0 + rs0;
        l1 = l1 * sc1 + rs1;

#pragma unroll
        for (int nb = 0; nb < 8; nb++) {
            acc[nb][0] *= sc0; acc[nb][1] *= sc0;
            acc[nb][2] *= sc1; acc[nb][3] *= sc1;
        }
        __syncwarp();

#pragma unroll
        for (int kk = 0; kk < 4; kk++) {
            const int kb = (kk << 3) + tig;
            const int p0 = prA * 36 + kb;
            const int p8 = prB * 36 + kb;
            unsigned pah[4] = {PSH[p0], PSH[p8], PSH[p0 + 4], PSH[p8 + 4]};
            unsigned pal[4] = {PSL[p0], PSL[p8], PSL[p0 + 4], PSL[p8 + 4]};
#pragma unroll
            for (int nb = 0; nb < 8; nb++) {
                const int rr = ((nb << 3) + gid) * 36 + kb;
                unsigned bh[2] = {VTH[rr], VTH[rr + 4]};
                unsigned bl[2] = {VTL[rr], VTL[rr + 4]};
                mma8(acc[nb], pal, bh);
                mma8(acc[nb], pah, bl);
                mma8(acc[nb], pah, bh);
            }
        }
    }

    const float rl0 = 1.0f / l0, rl1 = 1.0f / l1;
    const size_t o1 = ((rowb + jr0) << 9) + coff;
    const size_t o2 = ((rowb + jr1) << 9) + coff;
#pragma unroll
    for (int nb = 0; nb < 8; nb++) {
        const int c = (nb << 3) + (tig << 1);
        unsigned h0, l0u;
        cvt_hl(acc[nb][0] * rl0, h0, l0u); aoh[o1 + c]     = h0; aol[o1 + c]     = l0u;
        cvt_hl(acc[nb][1] * rl0, h0, l0u); aoh[o1 + c + 1] = h0; aol[o1 + c + 1] = l0u;
        cvt_hl(acc[nb][2] * rl1, h0, l0u); aoh[o2 + c]     = h0; aol[o2 + c]     = l0u;
        cvt_hl(acc[nb][3] * rl1, h0, l0u); aoh[o2 + c + 1] = h0; aol[o2 + c + 1] = l0u;
    }
}

// ---------------- kernel 4: LN2 + transpose to (B,D,S) output ----------------
__global__ __launch_bounds__(128) void k_ln2(
    const float* __restrict__ res, const float* __restrict__ g2,
    const float* __restrict__ b2, float* __restrict__ out)
{
    const int bs = blockIdx.x;
    const int b = bs >> 10, s = bs & 1023;
    const int t = threadIdx.x;
    float x[4]; float ls1 = 0.f, ls2 = 0.f;
#pragma unroll
    for (int r = 0; r < 4; r++) {
        x[r] = res[((size_t)bs << 9) + t + (r << 7)];
        ls1 += x[r]; ls2 += x[r] * x[r];
    }
    __shared__ float sa[4], sb[4];
#pragma unroll
    for (int o = 16; o; o >>= 1) {
        ls1 += __shfl_down_sync(0xffffffffu, ls1, o);
        ls2 += __shfl_down_sync(0xffffffffu, ls2, o);
    }
    if ((t & 31) == 0) { sa[t >> 5] = ls1; sb[t >> 5] = ls2; }
    __syncthreads();
    const float S1 = sa[0] + sa[1] + sa[2] + sa[3];
    const float S2 = sb[0] + sb[1] + sb[2] + sb[3];
    const float mean = S1 * (1.0f / 512.0f);
    const float var  = (S2 - 512.0f * mean * mean) * (1.0f / 511.0f);
    const float rstd = rsqrtf(var + 1e-5f);
    const float gg = g2[s], be = b2[s];
#pragma unroll
    for (int r = 0; r < 4; r++) {
        const int d = t + (r << 7);
        out[((size_t)((b << 9) + d) << 10) + s] = gg * (x[r] - mean) * rstd + be;
    }
}

// ---------------- launch -----------------------------------------------------
extern "C" void kernel_launch(void* const* d_in, const int* in_sizes, int n_in,
                              void* d_out, int out_size)
{
    const float* ts     = (const float*)d_in[0];
    const int*   te     = (const int*)  d_in[1];
    const float* conv_w = (const float*)d_in[2];
    const float* conv_b = (const float*)d_in[3];
    const float* pe     = (const float*)d_in[4];
    const float* ts_emb = (const float*)d_in[5];
    const float* g1     = (const float*)d_in[6];
    const float* b1     = (const float*)d_in[7];
    const float* Mw     = (const float*)d_in[8];
    const float* Wq     = (const float*)d_in[9];
    const float* Wk     = (const float*)d_in[10];
    const float* Wv     = (const float*)d_in[11];
    const float* Wo     = (const float*)d_in[12];
    const float* bo     = (const float*)d_in[13];
    const float* g2     = (const float*)d_in[14];
    const float* b2     = (const float*)d_in[15];
    float* out = (float*)d_out;

    float *pc, *pr;
    unsigned *n1h, *n1l, *dh, *dl, *pqh, *pql, *pkh, *pkl, *pvh, *pvl, *ah, *al;
    unsigned *wmh, *wml, *wqh, *wql, *wkh, *wkl, *wvh, *wvl, *woh, *wol;
    cudaGetSymbolAddress((void**)&pc,  g_conv);
    cudaGetSymbolAddress((void**)&pr,  g_res);
    cudaGetSymbolAddress((void**)&n1h, g_n1h); cudaGetSymbolAddress((void**)&n1l, g_n1l);
    cudaGetSymbolAddress((void**)&dh,  g_dh);  cudaGetSymbolAddress((void**)&dl,  g_dl);
    cudaGetSymbolAddress((void**)&pqh, g_qh);  cudaGetSymbolAddress((void**)&pql, g_ql);
    cudaGetSymbolAddress((void**)&pkh, g_kh);  cudaGetSymbolAddress((void**)&pkl, g_kl);
    cudaGetSymbolAddress((void**)&pvh, g_vh);  cudaGetSymbolAddress((void**)&pvl, g_vl);
    cudaGetSymbolAddress((void**)&ah,  g_ah);  cudaGetSymbolAddress((void**)&al,  g_al);
    cudaGetSymbolAddress((void**)&wmh, g_wmh); cudaGetSymbolAddress((void**)&wml, g_wml);
    cudaGetSymbolAddress((void**)&wqh, g_wqh); cudaGetSymbolAddress((void**)&wql, g_wql);
    cudaGetSymbolAddress((void**)&wkh, g_wkh); cudaGetSymbolAddress((void**)&wkl, g_wkl);
    cudaGetSymbolAddress((void**)&wvh, g_wvh); cudaGetSymbolAddress((void**)&wvl, g_wvl);
    cudaGetSymbolAddress((void**)&woh, g_woh); cudaGetSymbolAddress((void**)&wol, g_wol);

    const int GEMM_SMEM = 2 * GSTG * 4;           // 81920
    const int ATTN_SMEM = A_TOT * 4;              // 89088
    cudaFuncSetAttribute(tf32_gemm2, cudaFuncAttributeMaxDynamicSharedMemorySize, GEMM_SMEM);
    cudaFuncSetAttribute(k_attn2,    cudaFuncAttributeMaxDynamicSharedMemorySize, ATTN_SMEM);

    const int n4 = DDIM * DDIM / 4;   // 65536
    CvtTab tab;
    tab.in[0] = (const float4*)Mw; tab.oh[0] = (uint4*)wmh; tab.ol[0] = (uint4*)wml;
    tab.in[1] = (const float4*)Wq; tab.oh[1] = (uint4*)wqh; tab.ol[1] = (uint4*)wql;
    tab.in[2] = (const float4*)Wk; tab.oh[2] = (uint4*)wkh; tab.ol[2] = (uint4*)wkl;
    tab.in[3] = (const float4*)Wv; tab.oh[3] = (uint4*)wvh; tab.ol[3] = (uint4*)wvl;
    tab.in[4] = (const float4*)Wo; tab.oh[4] = (uint4*)woh; tab.ol[4] = (uint4*)wol;
    k_cvt5<<<dim3(n4 / 256, 5), 256>>>(tab, n4);

    k_embed<<<BSN, 128>>>(ts, conv_w, conv_b, pe, g1, b1, pc, n1h, n1l);

    dim3 gg(4, 128, 1);
    tf32_gemm2<<<gg, 256, GEMM_SMEM>>>(n1h, n1l, wmh, wml, nullptr, nullptr, nullptr, nullptr,
                                       dh, dl, nullptr, nullptr, nullptr, nullptr,
                                       nullptr, 0, te, ts_emb, nullptr);
    dim3 gq(4, 128, 3);
    tf32_gemm2<<<gq, 256, GEMM_SMEM>>>(dh, dl, wqh, wql, wkh, wkl, wvh, wvl,
                                       pqh, pql, pkh, pkl, pvh, pvl,
                                       nullptr, 4, nullptr, nullptr, nullptr);

    k_attn2<<<dim3(SSZ / 64, 8, BB), 128, ATTN_SMEM>>>(pqh, pql, pkh, pkl, pvh, pvl, ah, al);

    tf32_gemm2<<<gg, 256, GEMM_SMEM>>>(ah, al, woh, wol, nullptr, nullptr, nullptr, nullptr,
                                       nullptr, nullptr, nullptr, nullptr, nullptr, nullptr,
                                       pr, 3, nullptr, bo, pc);

    k_ln2<<<BSN, 128>>>(pr, g2, b2, out);
}

// round 5
// speedup vs baseline: 1.8897x; 1.5183x over previous
#include <cuda_runtime.h>
#include <cuda_bf16.h>
#include <math.h>

#define BB   16
#define SSZ  1024
#define DDIM 512
#define PDIM 256            // packed pairs per row
#define BSN  (BB*SSZ)       // 16384 rows
#define NEGF (-1e30f)

// ---------------- scratch (device globals: allocation-free) ----------------
// packed bf16 pairs: word i of row r = (x[2i] | x[2i+1]<<16)
__device__ float    g_conv [BSN*DDIM];
__device__ float    g_res  [BSN*DDIM];
__device__ unsigned g_n1h[BSN*PDIM], g_n1l[BSN*PDIM];
__device__ unsigned g_dh [BSN*PDIM], g_dl [BSN*PDIM];
__device__ unsigned g_qh [BSN*PDIM], g_ql [BSN*PDIM];
__device__ unsigned g_kh [BSN*PDIM], g_kl [BSN*PDIM];
__device__ unsigned g_vh [BSN*PDIM], g_vl [BSN*PDIM];
__device__ unsigned g_ah [BSN*PDIM], g_al [BSN*PDIM];
__device__ unsigned g_wmh[DDIM*PDIM], g_wml[DDIM*PDIM];
__device__ unsigned g_wqh[DDIM*PDIM], g_wql[DDIM*PDIM];
__device__ unsigned g_wkh[DDIM*PDIM], g_wkl[DDIM*PDIM];
__device__ unsigned g_wvh[DDIM*PDIM], g_wvl[DDIM*PDIM];
__device__ unsigned g_woh[DDIM*PDIM], g_wol[DDIM*PDIM];

// ---------------- helpers ----------------------------------------------------
__device__ __forceinline__ unsigned short bfu(float x) {
    __nv_bfloat16 b = __float2bfloat16_rn(x);
    return *(unsigned short*)&b;
}
__device__ __forceinline__ float bff(unsigned short u) {
    __nv_bfloat16 b = *(__nv_bfloat16*)&u;
    return __bfloat162float(b);
}
// split (x0,x1) into packed bf16 hi word + lo word
__device__ __forceinline__ void hl2(float x0, float x1, unsigned& H, unsigned& L) {
    const unsigned short h0 = bfu(x0), h1 = bfu(x1);
    const unsigned short l0 = bfu(x0 - bff(h0)), l1 = bfu(x1 - bff(h1));
    H = (unsigned)h0 | ((unsigned)h1 << 16);
    L = (unsigned)l0 | ((unsigned)l1 << 16);
}
__device__ __forceinline__ void mma16(float* c, const unsigned* a, const unsigned* b) {
    asm volatile(
        "mma.sync.aligned.m16n8k16.row.col.f32.bf16.bf16.f32 "
        "{%0,%1,%2,%3}, {%4,%5,%6,%7}, {%8,%9}, {%0,%1,%2,%3};\n"
        : "+f"(c[0]), "+f"(c[1]), "+f"(c[2]), "+f"(c[3])
        : "r"(a[0]), "r"(a[1]), "r"(a[2]), "r"(a[3]), "r"(b[0]), "r"(b[1]));
}
__device__ __forceinline__ unsigned su32(const void* p) {
    return (unsigned)__cvta_generic_to_shared(p);
}
#define CP16(d, s) asm volatile("cp.async.cg.shared.global [%0], [%1], 16;\n" :: "r"(d), "l"(s))
#define CP_COMMIT()  asm volatile("cp.async.commit_group;\n")
#define CP_WAIT1()   asm volatile("cp.async.wait_group 1;\n")

// ---------------- kernel: fp32 -> packed bf16 (hi, lo) for 5 weights ---------
struct CvtTab { const float4* in[5]; uint2* oh[5]; uint2* ol[5]; };
__global__ __launch_bounds__(256) void k_cvt5(CvtTab tab, int n4)
{
    const int w = blockIdx.y;
    int i = blockIdx.x * 256 + threadIdx.x;
    if (i >= n4) return;
    float4 v = tab.in[w][i];
    unsigned h0, l0, h1, l1;
    hl2(v.x, v.y, h0, l0);
    hl2(v.z, v.w, h1, l1);
    tab.oh[w][i] = make_uint2(h0, h1);
    tab.ol[w][i] = make_uint2(l0, l1);
}

// ---------------- kernel 1: conv + pe + gelu + LN1 (packed hi/lo out) --------
__global__ __launch_bounds__(128) void k_embed(
    const float* __restrict__ ts, const float* __restrict__ cw,
    const float* __restrict__ cb, const float* __restrict__ pe,
    const float* __restrict__ g1, const float* __restrict__ b1,
    float* __restrict__ convo, unsigned* __restrict__ n1h, unsigned* __restrict__ n1l)
{
    const int bs = blockIdx.x;
    const int b = bs >> 10, s = bs & 1023;
    const int t = threadIdx.x;
    const int d0 = t << 2;                       // 4 consecutive d per thread
    const float* tp = ts + ((size_t)b << 12) + (s << 2);
    const float t0 = tp[0], t1 = tp[1], t2 = tp[2], t3 = tp[3];

    const float4 cb4 = *(const float4*)(cb + d0);
    const float4 pe4 = *(const float4*)(pe + ((size_t)s << 9) + d0);

    float cvv[4], act[4];
    float ls1 = 0.f, ls2 = 0.f;
#pragma unroll
    for (int j = 0; j < 4; j++) {
        const float4 w = *(const float4*)(cw + ((d0 + j) << 2));
        float c = fmaf(t0, w.x, fmaf(t1, w.y, fmaf(t2, w.z, t3 * w.w)));
        c += ((const float*)&cb4)[j] + ((const float*)&pe4)[j];
        cvv[j] = c;
        const float a = 0.5f * c * (1.0f + erff(c * 0.70710678118654752f));
        act[j] = a; ls1 += a; ls2 += a * a;
    }
    *(float4*)(convo + ((size_t)bs << 9) + d0) = make_float4(cvv[0], cvv[1], cvv[2], cvv[3]);

    __shared__ float sa[4], sb[4];
#pragma unroll
    for (int o = 16; o; o >>= 1) {
        ls1 += __shfl_down_sync(0xffffffffu, ls1, o);
        ls2 += __shfl_down_sync(0xffffffffu, ls2, o);
    }
    if ((t & 31) == 0) { sa[t >> 5] = ls1; sb[t >> 5] = ls2; }
    __syncthreads();
    const float S1 = sa[0] + sa[1] + sa[2] + sa[3];
    const float S2 = sb[0] + sb[1] + sb[2] + sb[3];
    const float mean = S1 * (1.0f / 512.0f);
    const float var  = (S2 - 512.0f * mean * mean) * (1.0f / 511.0f);  // ddof=1
    const float rstd = rsqrtf(var + 1e-5f);
    const float gg = g1[s], be = b1[s];

    float v[4];
#pragma unroll
    for (int j = 0; j < 4; j++) v[j] = gg * (act[j] - mean) * rstd + be;
    unsigned H0, L0, H1, L1;
    hl2(v[0], v[1], H0, L0);
    hl2(v[2], v[3], H1, L1);
    const size_t pr = ((size_t)bs << 8) + (t << 1);
    *(uint2*)(n1h + pr) = make_uint2(H0, H1);
    *(uint2*)(n1l + pr) = make_uint2(L0, L1);
}

// ---------------- BF16x3 GEMM-NT, packed hi/lo operands ----------------------
// C[m,e] = sum_d A[m,d]*B[e,d].  M=16384, N=K=512, 128x128 tile, k-tile 16.
// mode 0: C = acc + ts_emb[te[b],e]   -> packed (C0h,C0l)
// mode 4: z=0: Q=acc*0.125 -> C0; z=1: K -> C1; z=2: V -> C2   (packed)
// mode 3: Cf = acc + bo[e] + conv[m,e]  (fp32)
#define SP2 12               // smem row stride in pairs (8 data + 4 pad)
#define GARR 1536            // words per array per stage (128*12)
#define GST  (4*GARR)        // 6144 words per stage
__global__ __launch_bounds__(256, 2) void bf16_gemm(
    const unsigned* __restrict__ Agh, const unsigned* __restrict__ Agl,
    const unsigned* __restrict__ B0h, const unsigned* __restrict__ B0l,
    const unsigned* __restrict__ B1h, const unsigned* __restrict__ B1l,
    const unsigned* __restrict__ B2h, const unsigned* __restrict__ B2l,
    unsigned* __restrict__ C0h, unsigned* __restrict__ C0l,
    unsigned* __restrict__ C1h, unsigned* __restrict__ C1l,
    unsigned* __restrict__ C2h, unsigned* __restrict__ C2l,
    float* __restrict__ Cf, int mode, const int* __restrict__ te,
    const float* __restrict__ aux1, const float* __restrict__ aux2)
{
    __shared__ unsigned gsm[2 * GST];            // 49152 B static

    const unsigned* Bgh = B0h; const unsigned* Bgl = B0l;
    unsigned* Ch = C0h; unsigned* Cl = C0l;
    float scale = 1.0f;
    if (mode == 4) {
        if (blockIdx.z == 1)      { Bgh = B1h; Bgl = B1l; Ch = C1h; Cl = C1l; }
        else if (blockIdx.z == 2) { Bgh = B2h; Bgl = B2l; Ch = C2h; Cl = C2l; }
        else                      { scale = 0.125f; }
    }

    const int t = threadIdx.x;
    const int row0 = blockIdx.y << 7, col0 = blockIdx.x << 7;
    const int lrow = t >> 1, lchunk = t & 1;     // 2 chunks of 4 pairs per row
    const size_t aoff = ((size_t)(row0 + lrow) << 8) + (lchunk << 2);
    const size_t boff = ((size_t)(col0 + lrow) << 8) + (lchunk << 2);
    const unsigned sbase = su32(gsm) + (unsigned)((lrow * SP2 + (lchunk << 2)) << 2);

    const int warp = t >> 5, lane = t & 31;
    const int gid = lane >> 2, tig = lane & 3;
    const int wm = warp & 1, wn = warp >> 1;

    float acc[4][4][4];
#pragma unroll
    for (int mt = 0; mt < 4; mt++)
#pragma unroll
        for (int nt = 0; nt < 4; nt++)
#pragma unroll
            for (int r = 0; r < 4; r++) acc[mt][nt][r] = 0.f;

#define GLOAD(kt, st) do {                                   \
        const unsigned kc = (unsigned)(kt) << 3;             \
        const unsigned sd = sbase + (st) * (GST << 2);       \
        CP16(sd,                 Agh + aoff + kc);           \
        CP16(sd + (GARR << 2),   Agl + aoff + kc);           \
        CP16(sd + (2*GARR << 2), Bgh + boff + kc);           \
        CP16(sd + (3*GARR << 2), Bgl + boff + kc);           \
    } while (0)

    GLOAD(0, 0); CP_COMMIT();
    GLOAD(1, 1); CP_COMMIT();

    for (int kt = 0; kt < 32; kt++) {
        CP_WAIT1();
        __syncthreads();
        const unsigned* S   = gsm + (kt & 1) * GST;
        const unsigned* SAh = S;
        const unsigned* SAl = S + GARR;
        const unsigned* SBh = S + 2*GARR;
        const unsigned* SBl = S + 3*GARR;

        unsigned bh[4][2], bl[4][2];
#pragma unroll
        for (int nt = 0; nt < 4; nt++) {
            const int rb = ((wn << 5) + (nt << 3) + gid) * SP2;
            bh[nt][0] = SBh[rb + tig]; bh[nt][1] = SBh[rb + tig + 4];
            bl[nt][0] = SBl[rb + tig]; bl[nt][1] = SBl[rb + tig + 4];
        }
#pragma unroll
        for (int mt = 0; mt < 4; mt++) {
            const int ra  = ((wm << 6) + (mt << 4) + gid) * SP2;
            const int ra8 = ra + 8 * SP2;
            unsigned ah[4] = {SAh[ra + tig], SAh[ra8 + tig], SAh[ra + tig + 4], SAh[ra8 + tig + 4]};
            unsigned al[4] = {SAl[ra + tig], SAl[ra8 + tig], SAl[ra + tig + 4], SAl[ra8 + tig + 4]};
#pragma unroll
            for (int nt = 0; nt < 4; nt++) {
                mma16(acc[mt][nt], al, bh[nt]);   // lo*hi
                mma16(acc[mt][nt], ah, bl[nt]);   // hi*lo
                mma16(acc[mt][nt], ah, bh[nt]);   // hi*hi
            }
        }
        __syncthreads();
        if (kt + 2 < 32) GLOAD(kt + 2, kt & 1);
        CP_COMMIT();
    }

    // ---- epilogue ----
    if (mode == 3) {
#pragma unroll
        for (int mt = 0; mt < 4; mt++) {
            const int r1 = row0 + (wm << 6) + (mt << 4) + gid;
            const int r2 = r1 + 8;
#pragma unroll
            for (int nt = 0; nt < 4; nt++) {
                const int c = col0 + (wn << 5) + (nt << 3) + (tig << 1);
                const float a0 = aux1[c], a1 = aux1[c + 1];
                float v0 = acc[mt][nt][0] + a0 + aux2[((size_t)r1 << 9) + c];
                float v1 = acc[mt][nt][1] + a1 + aux2[((size_t)r1 << 9) + c + 1];
                float v2 = acc[mt][nt][2] + a0 + aux2[((size_t)r2 << 9) + c];
                float v3 = acc[mt][nt][3] + a1 + aux2[((size_t)r2 << 9) + c + 1];
                *(float2*)(Cf + ((size_t)r1 << 9) + c) = make_float2(v0, v1);
                *(float2*)(Cf + ((size_t)r2 << 9) + c) = make_float2(v2, v3);
            }
        }
    } else {
        int e = 0;
        if (mode == 0) e = te[row0 >> 10];
#pragma unroll
        for (int mt = 0; mt < 4; mt++) {
            const int r1 = row0 + (wm << 6) + (mt << 4) + gid;
            const int r2 = r1 + 8;
#pragma unroll
            for (int nt = 0; nt < 4; nt++) {
                const int c = col0 + (wn << 5) + (nt << 3) + (tig << 1);
                float a0 = 0.f, a1 = 0.f;
                if (mode == 0) {
                    a0 = aux1[((size_t)e << 9) + c];
                    a1 = aux1[((size_t)e << 9) + c + 1];
                }
                const float v0 = acc[mt][nt][0] * scale + a0;
                const float v1 = acc[mt][nt][1] * scale + a1;
                const float v2 = acc[mt][nt][2] * scale + a0;
                const float v3 = acc[mt][nt][3] * scale + a1;
                unsigned H, L;
                const size_t i0p = ((size_t)r1 << 8) + (c >> 1);
                const size_t i1p = ((size_t)r2 << 8) + (c >> 1);
                hl2(v0, v1, H, L); Ch[i0p] = H; Cl[i0p] = L;
                hl2(v2, v3, H, L); Ch[i1p] = H; Cl[i1p] = L;
            }
        }
    }
}

// ---------------- bf16 tensor-core "transposed" causal flash attention -------
// out[j] = sum_{i<=j} softmax_i(k_j . q_i) v_i   (Q pre-scaled)
// 64 j rows resident (K), 4 warps x 16 j; i streamed in 32-row tiles.
__global__ __launch_bounds__(128) void k_attn3(
    const unsigned* __restrict__ qh, const unsigned* __restrict__ ql,
    const unsigned* __restrict__ kh, const unsigned* __restrict__ kl,
    const unsigned* __restrict__ vh, const unsigned* __restrict__ vl,
    unsigned* __restrict__ aoh, unsigned* __restrict__ aol)
{
    __shared__ unsigned KSH[64*36], KSL[64*36];   // K rows, 32 pairs + pad
    __shared__ unsigned QSH[32*36], QSL[32*36];   // Q rows, 32 pairs + pad
    __shared__ unsigned VTH[64*20], VTL[64*20];   // V^T: 64 c rows x 40 ushort
    __shared__ unsigned PSH[64*20], PSL[64*20];   // P: 64 j rows x 16 pairs + pad

    const int jt = (gridDim.x - 1) - blockIdx.x;  // big tiles first
    const int h = blockIdx.y, b = blockIdx.z;
    const int j0 = jt << 6;
    const int t = threadIdx.x, warp = t >> 5, lane = t & 31;
    const int gid = lane >> 2, tig = lane & 3;
    const size_t rowb = ((size_t)b << 10);
    const int coff2 = h << 5;                     // head offset in pairs

    // stage resident K tile
    {
        const int row = t >> 1, half = t & 1;
        const uint4* gh = (const uint4*)(kh + ((rowb + j0 + row) << 8) + coff2 + (half << 4));
        const uint4* gl = (const uint4*)(kl + ((rowb + j0 + row) << 8) + coff2 + (half << 4));
        uint4* dh_ = (uint4*)(KSH + row * 36 + (half << 4));
        uint4* dl_ = (uint4*)(KSL + row * 36 + (half << 4));
#pragma unroll
        for (int i = 0; i < 4; i++) { dh_[i] = gh[i]; dl_[i] = gl[i]; }
    }

    float m0 = NEGF, m1 = NEGF, l0 = 0.f, l1 = 0.f;
    float acc[8][4];
#pragma unroll
    for (int nb = 0; nb < 8; nb++)
#pragma unroll
        for (int r = 0; r < 4; r++) acc[nb][r] = 0.f;

    const int ntiles = (jt << 1) + 2;
    const int jr0 = j0 + (warp << 4) + gid, jr1 = jr0 + 8;
    const int prA = (warp << 4) + gid, prB = prA + 8;

    for (int it = 0; it < ntiles; ++it) {
        const int i0 = it << 5;
        __syncthreads();
        // stage Q tile (rows i0..i0+31)
        {
            const int row = t >> 2, q = t & 3;
            const uint4* gh = (const uint4*)(qh + ((rowb + i0 + row) << 8) + coff2 + (q << 3));
            const uint4* gl = (const uint4*)(ql + ((rowb + i0 + row) << 8) + coff2 + (q << 3));
            uint4* dh_ = (uint4*)(QSH + row * 36 + (q << 3));
            uint4* dl_ = (uint4*)(QSL + row * 36 + (q << 3));
            dh_[0] = gh[0]; dh_[1] = gh[1];
            dl_[0] = gl[0]; dl_[1] = gl[1];
        }
        // stage V transposed (VT[c][i] as ushort, i-stride 40)
        {
            const int i = t & 31, cp = t >> 5;    // 16 c per group
            const unsigned* gh = vh + ((rowb + i0 + i) << 8) + coff2 + (cp << 3);
            const unsigned* gl = vl + ((rowb + i0 + i) << 8) + coff2 + (cp << 3);
            unsigned short* H16 = (unsigned short*)VTH;
            unsigned short* L16 = (unsigned short*)VTL;
#pragma unroll
            for (int w = 0; w < 8; w++) {
                const unsigned x = gh[w], y = gl[w];
                const int c = (cp << 4) + (w << 1);
                H16[c * 40 + i]       = (unsigned short)x;
                H16[(c + 1) * 40 + i] = (unsigned short)(x >> 16);
                L16[c * 40 + i]       = (unsigned short)y;
                L16[(c + 1) * 40 + i] = (unsigned short)(y >> 16);
            }
        }
        __syncthreads();

        // ---- scores: m=j(16/warp), n=i(32), k=c(64) -> 4 k16 steps ----
        float s[4][4];
#pragma unroll
        for (int nb = 0; nb < 4; nb++)
#pragma unroll
            for (int r = 0; r < 4; r++) s[nb][r] = 0.f;
#pragma unroll
        for (int ks = 0; ks < 4; ks++) {
            const int r0 = prA * 36 + (ks << 3) + tig;
            const int r8 = r0 + 8 * 36;
            unsigned ah[4] = {KSH[r0], KSH[r8], KSH[r0 + 4], KSH[r8 + 4]};
            unsigned al[4] = {KSL[r0], KSL[r8], KSL[r0 + 4], KSL[r8 + 4]};
#pragma unroll
            for (int nb = 0; nb < 4; nb++) {
                const int rr = ((nb << 3) + gid) * 36 + (ks << 3) + tig;
                unsigned bh[2] = {QSH[rr], QSH[rr + 4]};
                unsigned bl[2] = {QSL[rr], QSL[rr + 4]};
                mma16(s[nb], al, bh);
                mma16(s[nb], ah, bl);
                mma16(s[nb], ah, bh);
            }
        }

        // ---- causal mask (last two tiles only) ----
        if (it >= ntiles - 2) {
#pragma unroll
            for (int nb = 0; nb < 4; nb++) {
                const int c = i0 + (nb << 3) + (tig << 1);
                if (c     > jr0) s[nb][0] = NEGF;
                if (c + 1 > jr0) s[nb][1] = NEGF;
                if (c     > jr1) s[nb][2] = NEGF;
                if (c + 1 > jr1) s[nb][3] = NEGF;
            }
        }

        // ---- online softmax (rows prA, prB per thread-quad) ----
        float mt0 = NEGF, mt1 = NEGF;
#pragma unroll
        for (int nb = 0; nb < 4; nb++) {
            mt0 = fmaxf(mt0, fmaxf(s[nb][0], s[nb][1]));
            mt1 = fmaxf(mt1, fmaxf(s[nb][2], s[nb][3]));
        }
        mt0 = fmaxf(mt0, __shfl_xor_sync(0xffffffffu, mt0, 1));
        mt0 = fmaxf(mt0, __shfl_xor_sync(0xffffffffu, mt0, 2));
        mt1 = fmaxf(mt1, __shfl_xor_sync(0xffffffffu, mt1, 1));
        mt1 = fmaxf(mt1, __shfl_xor_sync(0xffffffffu, mt1, 2));
        const float mn0 = fmaxf(m0, mt0), mn1 = fmaxf(m1, mt1);
        const float sc0 = __expf(m0 - mn0), sc1 = __expf(m1 - mn1);
        m0 = mn0; m1 = mn1;

        float rs0 = 0.f, rs1 = 0.f;
#pragma unroll
        for (int nb = 0; nb < 4; nb++) {
            s[nb][0] = __expf(s[nb][0] - mn0);
            s[nb][1] = __expf(s[nb][1] - mn0);
            s[nb][2] = __expf(s[nb][2] - mn1);
            s[nb][3] = __expf(s[nb][3] - mn1);
            rs0 += s[nb][0] + s[nb][1];
            rs1 += s[nb][2] + s[nb][3];
            unsigned H, L;
            const int pp = (nb << 2) + tig;
            hl2(s[nb][0], s[nb][1], H, L); PSH[prA * 20 + pp] = H; PSL[prA * 20 + pp] = L;
            hl2(s[nb][2], s[nb][3], H, L); PSH[prB * 20 + pp] = H; PSL[prB * 20 + pp] = L;
        }
        rs0 += __shfl_xor_sync(0xffffffffu, rs0, 1);
        rs0 += __shfl_xor_sync(0xffffffffu, rs0, 2);
        rs1 += __shfl_xor_sync(0xffffffffu, rs1, 1);
        rs1 += __shfl_xor_sync(0xffffffffu, rs1, 2);
        l0 = l0 * sc0 + rs0;
        l1 = l1 * sc1 + rs1;

#pragma unroll
        for (int nb = 0; nb < 8; nb++) {
            acc[nb][0] *= sc0; acc[nb][1] *= sc0;
            acc[nb][2] *= sc1; acc[nb][3] *= sc1;
        }
        __syncwarp();

        // ---- PV: m=j(16/warp), n=c(64), k=i(32) -> 2 k16 steps ----
#pragma unroll
        for (int kk = 0; kk < 2; kk++) {
            const int p0 = prA * 20 + (kk << 3) + tig;
            const int p8 = prB * 20 + (kk << 3) + tig;
            unsigned pah[4] = {PSH[p0], PSH[p8], PSH[p0 + 4], PSH[p8 + 4]};
            unsigned pal[4] = {PSL[p0], PSL[p8], PSL[p0 + 4], PSL[p8 + 4]};
#pragma unroll
            for (int nb = 0; nb < 8; nb++) {
                const int rr = ((nb << 3) + gid) * 20 + (kk << 3) + tig;
                unsigned bh[2] = {VTH[rr], VTH[rr + 4]};
                unsigned bl[2] = {VTL[rr], VTL[rr + 4]};
                mma16(acc[nb], pal, bh);
                mma16(acc[nb], pah, bl);
                mma16(acc[nb], pah, bh);
            }
        }
    }

    // ---- epilogue: /l, pack, store ----
    const float rl0 = 1.0f / l0, rl1 = 1.0f / l1;
    const size_t o1 = ((rowb + jr0) << 8) + coff2;
    const size_t o2 = ((rowb + jr1) << 8) + coff2;
#pragma unroll
    for (int nb = 0; nb < 8; nb++) {
        const int pp = (nb << 2) + tig;
        unsigned H, L;
        hl2(acc[nb][0] * rl0, acc[nb][1] * rl0, H, L);
        aoh[o1 + pp] = H; aol[o1 + pp] = L;
        hl2(acc[nb][2] * rl1, acc[nb][3] * rl1, H, L);
        aoh[o2 + pp] = H; aol[o2 + pp] = L;
    }
}

// ---------------- kernel 4: LN2 + transpose to (B,D,S) output ----------------
__global__ __launch_bounds__(128) void k_ln2(
    const float* __restrict__ res, const float* __restrict__ g2,
    const float* __restrict__ b2, float* __restrict__ out)
{
    const int bs = blockIdx.x;
    const int b = bs >> 10, s = bs & 1023;
    const int t = threadIdx.x;
    float x[4]; float ls1 = 0.f, ls2 = 0.f;
#pragma unroll
    for (int r = 0; r < 4; r++) {
        x[r] = res[((size_t)bs << 9) + t + (r << 7)];
        ls1 += x[r]; ls2 += x[r] * x[r];
    }
    __shared__ float sa[4], sb[4];
#pragma unroll
    for (int o = 16; o; o >>= 1) {
        ls1 += __shfl_down_sync(0xffffffffu, ls1, o);
        ls2 += __shfl_down_sync(0xffffffffu, ls2, o);
    }
    if ((t & 31) == 0) { sa[t >> 5] = ls1; sb[t >> 5] = ls2; }
    __syncthreads();
    const float S1 = sa[0] + sa[1] + sa[2] + sa[3];
    const float S2 = sb[0] + sb[1] + sb[2] + sb[3];
    const float mean = S1 * (1.0f / 512.0f);
    const float var  = (S2 - 512.0f * mean * mean) * (1.0f / 511.0f);
    const float rstd = rsqrtf(var + 1e-5f);
    const float gg = g2[s], be = b2[s];
#pragma unroll
    for (int r = 0; r < 4; r++) {
        const int d = t + (r << 7);
        out[((size_t)((b << 9) + d) << 10) + s] = gg * (x[r] - mean) * rstd + be;
    }
}

// ---------------- launch -----------------------------------------------------
extern "C" void kernel_launch(void* const* d_in, const int* in_sizes, int n_in,
                              void* d_out, int out_size)
{
    const float* ts     = (const float*)d_in[0];
    const int*   te     = (const int*)  d_in[1];
    const float* conv_w = (const float*)d_in[2];
    const float* conv_b = (const float*)d_in[3];
    const float* pe     = (const float*)d_in[4];
    const float* ts_emb = (const float*)d_in[5];
    const float* g1     = (const float*)d_in[6];
    const float* b1     = (const float*)d_in[7];
    const float* Mw     = (const float*)d_in[8];
    const float* Wq     = (const float*)d_in[9];
    const float* Wk     = (const float*)d_in[10];
    const float* Wv     = (const float*)d_in[11];
    const float* Wo     = (const float*)d_in[12];
    const float* bo     = (const float*)d_in[13];
    const float* g2     = (const float*)d_in[14];
    const float* b2     = (const float*)d_in[15];
    float* out = (float*)d_out;

    float *pc, *pr;
    unsigned *n1h, *n1l, *dh, *dl, *pqh, *pql, *pkh, *pkl, *pvh, *pvl, *ah, *al;
    unsigned *wmh, *wml, *wqh, *wql, *wkh, *wkl, *wvh, *wvl, *woh, *wol;
    cudaGetSymbolAddress((void**)&pc,  g_conv);
    cudaGetSymbolAddress((void**)&pr,  g_res);
    cudaGetSymbolAddress((void**)&n1h, g_n1h); cudaGetSymbolAddress((void**)&n1l, g_n1l);
    cudaGetSymbolAddress((void**)&dh,  g_dh);  cudaGetSymbolAddress((void**)&dl,  g_dl);
    cudaGetSymbolAddress((void**)&pqh, g_qh);  cudaGetSymbolAddress((void**)&pql, g_ql);
    cudaGetSymbolAddress((void**)&pkh, g_kh);  cudaGetSymbolAddress((void**)&pkl, g_kl);
    cudaGetSymbolAddress((void**)&pvh, g_vh);  cudaGetSymbolAddress((void**)&pvl, g_vl);
    cudaGetSymbolAddress((void**)&ah,  g_ah);  cudaGetSymbolAddress((void**)&al,  g_al);
    cudaGetSymbolAddress((void**)&wmh, g_wmh); cudaGetSymbolAddress((void**)&wml, g_wml);
    cudaGetSymbolAddress((void**)&wqh, g_wqh); cudaGetSymbolAddress((void**)&wql, g_wql);
    cudaGetSymbolAddress((void**)&wkh, g_wkh); cudaGetSymbolAddress((void**)&wkl, g_wkl);
    cudaGetSymbolAddress((void**)&wvh, g_wvh); cudaGetSymbolAddress((void**)&wvl, g_wvl);
    cudaGetSymbolAddress((void**)&woh, g_woh); cudaGetSymbolAddress((void**)&wol, g_wol);

    // weight packing (once per launch)
    const int n4 = DDIM * DDIM / 4;   // 65536 float4 per weight
    CvtTab tab;
    tab.in[0] = (const float4*)Mw; tab.oh[0] = (uint2*)wmh; tab.ol[0] = (uint2*)wml;
    tab.in[1] = (const float4*)Wq; tab.oh[1] = (uint2*)wqh; tab.ol[1] = (uint2*)wql;
    tab.in[2] = (const float4*)Wk; tab.oh[2] = (uint2*)wkh; tab.ol[2] = (uint2*)wkl;
    tab.in[3] = (const float4*)Wv; tab.oh[3] = (uint2*)wvh; tab.ol[3] = (uint2*)wvl;
    tab.in[4] = (const float4*)Wo; tab.oh[4] = (uint2*)woh; tab.ol[4] = (uint2*)wol;
    k_cvt5<<<dim3(n4 / 256, 5), 256>>>(tab, n4);

    k_embed<<<BSN, 128>>>(ts, conv_w, conv_b, pe, g1, b1, pc, n1h, n1l);

    dim3 gg(4, 128, 1);
    // dense = M @ n1 + ts_emb gather -> packed (dh, dl)
    bf16_gemm<<<gg, 256>>>(n1h, n1l, wmh, wml, nullptr, nullptr, nullptr, nullptr,
                           dh, dl, nullptr, nullptr, nullptr, nullptr,
                           nullptr, 0, te, ts_emb, nullptr);
    // fused QKV (z=0: Q*0.125, z=1: K, z=2: V) -> packed
    dim3 gq(4, 128, 3);
    bf16_gemm<<<gq, 256>>>(dh, dl, wqh, wql, wkh, wkl, wvh, wvl,
                           pqh, pql, pkh, pkl, pvh, pvl,
                           nullptr, 4, nullptr, nullptr, nullptr);

    k_attn3<<<dim3(SSZ / 64, 8, BB), 128>>>(pqh, pql, pkh, pkl, pvh, pvl, ah, al);

    // res = Wo @ attn + bo + conv residual (fp32)
    bf16_gemm<<<gg, 256>>>(ah, al, woh, wol, nullptr, nullptr, nullptr, nullptr,
                           nullptr, nullptr, nullptr, nullptr, nullptr, nullptr,
                           pr, 3, nullptr, bo, pc);

    k_ln2<<<BSN, 128>>>(pr, g2, b2, out);
}

// round 7
// speedup vs baseline: 2.6989x; 1.4282x over previous
#include <cuda_runtime.h>
#include <cuda_bf16.h>
#include <math.h>

#define BB   16
#define SSZ  1024
#define DDIM 512
#define PDIM 256            // packed pairs per row
#define BSN  (BB*SSZ)       // 16384 rows
#define NEGF (-1e30f)

// ---------------- scratch (device globals: allocation-free) ----------------
__device__ float    g_conv [BSN*DDIM];
__device__ float    g_res  [BSN*DDIM];
__device__ unsigned g_n1h[BSN*PDIM], g_n1l[BSN*PDIM];
__device__ unsigned g_dh [BSN*PDIM], g_dl [BSN*PDIM];
__device__ unsigned g_qh [BSN*PDIM], g_ql [BSN*PDIM];
__device__ unsigned g_kh [BSN*PDIM], g_kl [BSN*PDIM];
__device__ unsigned g_vh [BSN*PDIM], g_vl [BSN*PDIM];
__device__ unsigned g_ah [BSN*PDIM], g_al [BSN*PDIM];
__device__ unsigned g_wmh[DDIM*PDIM], g_wml[DDIM*PDIM];
__device__ unsigned g_wqh[DDIM*PDIM], g_wql[DDIM*PDIM];
__device__ unsigned g_wkh[DDIM*PDIM], g_wkl[DDIM*PDIM];
__device__ unsigned g_wvh[DDIM*PDIM], g_wvl[DDIM*PDIM];
__device__ unsigned g_woh[DDIM*PDIM], g_wol[DDIM*PDIM];

// ---------------- helpers ----------------------------------------------------
__device__ __forceinline__ unsigned short bfu(float x) {
    __nv_bfloat16 b = __float2bfloat16_rn(x);
    return *(unsigned short*)&b;
}
__device__ __forceinline__ float bff(unsigned short u) {
    __nv_bfloat16 b = *(__nv_bfloat16*)&u;
    return __bfloat162float(b);
}
__device__ __forceinline__ void hl2(float x0, float x1, unsigned& H, unsigned& L) {
    const unsigned short h0 = bfu(x0), h1 = bfu(x1);
    const unsigned short l0 = bfu(x0 - bff(h0)), l1 = bfu(x1 - bff(h1));
    H = (unsigned)h0 | ((unsigned)h1 << 16);
    L = (unsigned)l0 | ((unsigned)l1 << 16);
}
__device__ __forceinline__ void mma16(float* c, const unsigned* a, const unsigned* b) {
    asm volatile(
        "mma.sync.aligned.m16n8k16.row.col.f32.bf16.bf16.f32 "
        "{%0,%1,%2,%3}, {%4,%5,%6,%7}, {%8,%9}, {%0,%1,%2,%3};\n"
        : "+f"(c[0]), "+f"(c[1]), "+f"(c[2]), "+f"(c[3])
        : "r"(a[0]), "r"(a[1]), "r"(a[2]), "r"(a[3]), "r"(b[0]), "r"(b[1]));
}
__device__ __forceinline__ void ldsm_x4(unsigned& r0, unsigned& r1, unsigned& r2,
                                        unsigned& r3, unsigned addr) {
    asm volatile("ldmatrix.sync.aligned.m8n8.x4.shared.b16 {%0,%1,%2,%3}, [%4];"
        : "=r"(r0), "=r"(r1), "=r"(r2), "=r"(r3) : "r"(addr));
}
__device__ __forceinline__ void ldsm_x4t(unsigned& r0, unsigned& r1, unsigned& r2,
                                         unsigned& r3, unsigned addr) {
    asm volatile("ldmatrix.sync.aligned.m8n8.x4.trans.shared.b16 {%0,%1,%2,%3}, [%4];"
        : "=r"(r0), "=r"(r1), "=r"(r2), "=r"(r3) : "r"(addr));
}
__device__ __forceinline__ unsigned su32(const void* p) {
    return (unsigned)__cvta_generic_to_shared(p);
}
#define CP16(d, s) asm volatile("cp.async.cg.shared.global [%0], [%1], 16;\n" :: "r"(d), "l"(s))
#define CP_COMMIT()  asm volatile("cp.async.commit_group;\n")
#define CP_WAIT1()   asm volatile("cp.async.wait_group 1;\n")

// ---------------- kernel: fp32 -> packed bf16 (hi, lo) for 5 weights ---------
struct CvtTab { const float4* in[5]; uint2* oh[5]; uint2* ol[5]; };
__global__ __launch_bounds__(256) void k_cvt5(CvtTab tab, int n4)
{
    const int w = blockIdx.y;
    int i = blockIdx.x * 256 + threadIdx.x;
    if (i >= n4) return;
    float4 v = tab.in[w][i];
    unsigned h0, l0, h1, l1;
    hl2(v.x, v.y, h0, l0);
    hl2(v.z, v.w, h1, l1);
    tab.oh[w][i] = make_uint2(h0, h1);
    tab.ol[w][i] = make_uint2(l0, l1);
}

// ---------------- kernel 1: conv + pe + gelu + LN1 (packed hi/lo out) --------
__global__ __launch_bounds__(128) void k_embed(
    const float* __restrict__ ts, const float* __restrict__ cw,
    const float* __restrict__ cb, const float* __restrict__ pe,
    const float* __restrict__ g1, const float* __restrict__ b1,
    float* __restrict__ convo, unsigned* __restrict__ n1h, unsigned* __restrict__ n1l)
{
    const int bs = blockIdx.x;
    const int b = bs >> 10, s = bs & 1023;
    const int t = threadIdx.x;
    const int d0 = t << 2;
    const float* tp = ts + ((size_t)b << 12) + (s << 2);
    const float t0 = tp[0], t1 = tp[1], t2 = tp[2], t3 = tp[3];

    const float4 cb4 = *(const float4*)(cb + d0);
    const float4 pe4 = *(const float4*)(pe + ((size_t)s << 9) + d0);

    float cvv[4], act[4];
    float ls1 = 0.f, ls2 = 0.f;
#pragma unroll
    for (int j = 0; j < 4; j++) {
        const float4 w = *(const float4*)(cw + ((d0 + j) << 2));
        float c = fmaf(t0, w.x, fmaf(t1, w.y, fmaf(t2, w.z, t3 * w.w)));
        c += ((const float*)&cb4)[j] + ((const float*)&pe4)[j];
        cvv[j] = c;
        const float a = 0.5f * c * (1.0f + erff(c * 0.70710678118654752f));
        act[j] = a; ls1 += a; ls2 += a * a;
    }
    *(float4*)(convo + ((size_t)bs << 9) + d0) = make_float4(cvv[0], cvv[1], cvv[2], cvv[3]);

    __shared__ float sa[4], sb[4];
#pragma unroll
    for (int o = 16; o; o >>= 1) {
        ls1 += __shfl_down_sync(0xffffffffu, ls1, o);
        ls2 += __shfl_down_sync(0xffffffffu, ls2, o);
    }
    if ((t & 31) == 0) { sa[t >> 5] = ls1; sb[t >> 5] = ls2; }
    __syncthreads();
    const float S1 = sa[0] + sa[1] + sa[2] + sa[3];
    const float S2 = sb[0] + sb[1] + sb[2] + sb[3];
    const float mean = S1 * (1.0f / 512.0f);
    const float var  = (S2 - 512.0f * mean * mean) * (1.0f / 511.0f);  // ddof=1
    const float rstd = rsqrtf(var + 1e-5f);
    const float gg = g1[s], be = b1[s];

    float v[4];
#pragma unroll
    for (int j = 0; j < 4; j++) v[j] = gg * (act[j] - mean) * rstd + be;
    unsigned H0, L0, H1, L1;
    hl2(v[0], v[1], H0, L0);
    hl2(v[2], v[3], H1, L1);
    const size_t pr = ((size_t)bs << 8) + (t << 1);
    *(uint2*)(n1h + pr) = make_uint2(H0, H1);
    *(uint2*)(n1l + pr) = make_uint2(L0, L1);
}

// ---------------- BF16x3 GEMM-NT (round-5 proven version, static smem) -------
#define SP2 12               // smem row stride in pairs (8 data + 4 pad)
#define GARR 1536            // words per array per stage (128*12)
#define GST  (4*GARR)        // 6144 words per stage
__global__ __launch_bounds__(256, 2) void bf16_gemm(
    const unsigned* __restrict__ Agh, const unsigned* __restrict__ Agl,
    const unsigned* __restrict__ B0h, const unsigned* __restrict__ B0l,
    const unsigned* __restrict__ B1h, const unsigned* __restrict__ B1l,
    const unsigned* __restrict__ B2h, const unsigned* __restrict__ B2l,
    unsigned* __restrict__ C0h, unsigned* __restrict__ C0l,
    unsigned* __restrict__ C1h, unsigned* __restrict__ C1l,
    unsigned* __restrict__ C2h, unsigned* __restrict__ C2l,
    float* __restrict__ Cf, int mode, const int* __restrict__ te,
    const float* __restrict__ aux1, const float* __restrict__ aux2)
{
    __shared__ unsigned gsm[2 * GST];            // 49152 B static

    const unsigned* Bgh = B0h; const unsigned* Bgl = B0l;
    unsigned* Ch = C0h; unsigned* Cl = C0l;
    float scale = 1.0f;
    if (mode == 4) {
        if (blockIdx.z == 1)      { Bgh = B1h; Bgl = B1l; Ch = C1h; Cl = C1l; }
        else if (blockIdx.z == 2) { Bgh = B2h; Bgl = B2l; Ch = C2h; Cl = C2l; }
        else                      { scale = 0.125f; }
    }

    const int t = threadIdx.x;
    const int row0 = blockIdx.y << 7, col0 = blockIdx.x << 7;
    const int lrow = t >> 1, lchunk = t & 1;
    const size_t aoff = ((size_t)(row0 + lrow) << 8) + (lchunk << 2);
    const size_t boff = ((size_t)(col0 + lrow) << 8) + (lchunk << 2);
    const unsigned sbase = su32(gsm) + (unsigned)((lrow * SP2 + (lchunk << 2)) << 2);

    const int warp = t >> 5, lane = t & 31;
    const int gid = lane >> 2, tig = lane & 3;
    const int wm = warp & 1, wn = warp >> 1;

    float acc[4][4][4];
#pragma unroll
    for (int mt = 0; mt < 4; mt++)
#pragma unroll
        for (int nt = 0; nt < 4; nt++)
#pragma unroll
            for (int r = 0; r < 4; r++) acc[mt][nt][r] = 0.f;

#define GLOAD(kt, st) do {                                   \
        const unsigned kc = (unsigned)(kt) << 3;             \
        const unsigned sd = sbase + (st) * (GST << 2);       \
        CP16(sd,                 Agh + aoff + kc);           \
        CP16(sd + (GARR << 2),   Agl + aoff + kc);           \
        CP16(sd + (2*GARR << 2), Bgh + boff + kc);           \
        CP16(sd + (3*GARR << 2), Bgl + boff + kc);           \
    } while (0)

    GLOAD(0, 0); CP_COMMIT();
    GLOAD(1, 1); CP_COMMIT();

    for (int kt = 0; kt < 32; kt++) {
        CP_WAIT1();
        __syncthreads();
        const unsigned* S   = gsm + (kt & 1) * GST;
        const unsigned* SAh = S;
        const unsigned* SAl = S + GARR;
        const unsigned* SBh = S + 2*GARR;
        const unsigned* SBl = S + 3*GARR;

        unsigned bh[4][2], bl[4][2];
#pragma unroll
        for (int nt = 0; nt < 4; nt++) {
            const int rb = ((wn << 5) + (nt << 3) + gid) * SP2;
            bh[nt][0] = SBh[rb + tig]; bh[nt][1] = SBh[rb + tig + 4];
            bl[nt][0] = SBl[rb + tig]; bl[nt][1] = SBl[rb + tig + 4];
        }
#pragma unroll
        for (int mt = 0; mt < 4; mt++) {
            const int ra  = ((wm << 6) + (mt << 4) + gid) * SP2;
            const int ra8 = ra + 8 * SP2;
            unsigned ah[4] = {SAh[ra + tig], SAh[ra8 + tig], SAh[ra + tig + 4], SAh[ra8 + tig + 4]};
            unsigned al[4] = {SAl[ra + tig], SAl[ra8 + tig], SAl[ra + tig + 4], SAl[ra8 + tig + 4]};
#pragma unroll
            for (int nt = 0; nt < 4; nt++) {
                mma16(acc[mt][nt], al, bh[nt]);
                mma16(acc[mt][nt], ah, bl[nt]);
                mma16(acc[mt][nt], ah, bh[nt]);
            }
        }
        __syncthreads();
        if (kt + 2 < 32) GLOAD(kt + 2, kt & 1);
        CP_COMMIT();
    }

    // ---- epilogue ----
    if (mode == 3) {
#pragma unroll
        for (int mt = 0; mt < 4; mt++) {
            const int r1 = row0 + (wm << 6) + (mt << 4) + gid;
            const int r2 = r1 + 8;
#pragma unroll
            for (int nt = 0; nt < 4; nt++) {
                const int c = col0 + (wn << 5) + (nt << 3) + (tig << 1);
                const float a0 = aux1[c], a1 = aux1[c + 1];
                float v0 = acc[mt][nt][0] + a0 + aux2[((size_t)r1 << 9) + c];
                float v1 = acc[mt][nt][1] + a1 + aux2[((size_t)r1 << 9) + c + 1];
                float v2 = acc[mt][nt][2] + a0 + aux2[((size_t)r2 << 9) + c];
                float v3 = acc[mt][nt][3] + a1 + aux2[((size_t)r2 << 9) + c + 1];
                *(float2*)(Cf + ((size_t)r1 << 9) + c) = make_float2(v0, v1);
                *(float2*)(Cf + ((size_t)r2 << 9) + c) = make_float2(v2, v3);
            }
        }
    } else {
        int e = 0;
        if (mode == 0) e = te[row0 >> 10];
#pragma unroll
        for (int mt = 0; mt < 4; mt++) {
            const int r1 = row0 + (wm << 6) + (mt << 4) + gid;
            const int r2 = r1 + 8;
#pragma unroll
            for (int nt = 0; nt < 4; nt++) {
                const int c = col0 + (wn << 5) + (nt << 3) + (tig << 1);
                float a0 = 0.f, a1 = 0.f;
                if (mode == 0) {
                    a0 = aux1[((size_t)e << 9) + c];
                    a1 = aux1[((size_t)e << 9) + c + 1];
                }
                const float v0 = acc[mt][nt][0] * scale + a0;
                const float v1 = acc[mt][nt][1] * scale + a1;
                const float v2 = acc[mt][nt][2] * scale + a0;
                const float v3 = acc[mt][nt][3] * scale + a1;
                unsigned H, L;
                const size_t i0p = ((size_t)r1 << 8) + (c >> 1);
                const size_t i1p = ((size_t)r2 << 8) + (c >> 1);
                hl2(v0, v1, H, L); Ch[i0p] = H; Cl[i0p] = L;
                hl2(v2, v3, H, L); Ch[i1p] = H; Cl[i1p] = L;
            }
        }
    }
}

// ---------------- FA2-style bf16x3 attention, static 36KB smem ---------------
// out[j] = sum_{i<=j} softmax_i(k_j . q_i) v_i   (Q pre-scaled)
// 64 j rows resident (4 warps x 16); i streamed in 32-row tiles, double-buffered.
// K fragments loaded DIRECTLY from global into registers (no K smem).
// Q via ldmatrix.x4; V via ldmatrix.x4.trans; P stays in registers.
// Stage layout (words): QH 0 | QL 1152 | VH 2304 | VL 3456 ; stage size 4608.
#define RS 36
#define STW 4608
__global__ __launch_bounds__(128, 2) void k_attn5(
    const unsigned* __restrict__ qh, const unsigned* __restrict__ ql,
    const unsigned* __restrict__ kh, const unsigned* __restrict__ kl,
    const unsigned* __restrict__ vh, const unsigned* __restrict__ vl,
    unsigned* __restrict__ aoh, unsigned* __restrict__ aol)
{
    __shared__ unsigned smw[2 * STW];            // 36864 B static

    const int jt = (gridDim.x - 1) - blockIdx.x; // big tiles first
    const int h = blockIdx.y, b = blockIdx.z;
    const int j0 = jt << 6;
    const int t = threadIdx.x, warp = t >> 5, lane = t & 31;
    const int gid = lane >> 2, tig = lane & 3;
    const size_t rowb = ((size_t)b << 10);
    const int coff2 = h << 5;
    const unsigned sbase = su32(smw);

    // loader mapping: 4 threads per row; each does 2 CP16 per array
    const int lrow = t >> 2;                     // 0..31
    const int lsub = (t & 3) << 3;               // word offset 0,8,16,24

#define LOADQV(i0_, st_) do {                                                   \
        const size_t g_ = ((rowb + (unsigned)(i0_) + lrow) << 8) + coff2 + lsub; \
        const unsigned s_ = sbase + (((st_) * STW + lrow * RS + lsub) << 2);     \
        CP16(s_,                  qh + g_);                                     \
        CP16(s_ + 16,             qh + g_ + 4);                                 \
        CP16(s_ + (1152 << 2),      ql + g_);                                   \
        CP16(s_ + (1152 << 2) + 16, ql + g_ + 4);                               \
        CP16(s_ + (2304 << 2),      vh + g_);                                   \
        CP16(s_ + (2304 << 2) + 16, vh + g_ + 4);                               \
        CP16(s_ + (3456 << 2),      vl + g_);                                   \
        CP16(s_ + (3456 << 2) + 16, vl + g_ + 4);                               \
    } while (0)

    const int ntiles = (jt << 1) + 2;

    LOADQV(0, 0); CP_COMMIT();
    if (ntiles > 1) LOADQV(32, 1);
    CP_COMMIT();

    // ---- K fragments straight from global (A-operand layout) ----
    // a0=(row, pair p), a1=(row+8, p), a2=(row, p+4), a3=(row+8, p+4); p = ks*8+tig
    const int krow = j0 + (warp << 4) + gid;
    const size_t kg0 = ((rowb + krow) << 8) + coff2;
    const size_t kg8 = ((rowb + krow + 8) << 8) + coff2;
    unsigned kfh[4][4], kfl[4][4];
#pragma unroll
    for (int ks = 0; ks < 4; ks++) {
        const int p = (ks << 3) + tig;
        kfh[ks][0] = kh[kg0 + p];     kfh[ks][1] = kh[kg8 + p];
        kfh[ks][2] = kh[kg0 + p + 4]; kfh[ks][3] = kh[kg8 + p + 4];
        kfl[ks][0] = kl[kg0 + p];     kfl[ks][1] = kl[kg8 + p];
        kfl[ks][2] = kl[kg0 + p + 4]; kfl[ks][3] = kl[kg8 + p + 4];
    }

    // ldmatrix per-thread address components
    const int qrowrel = (lane & 7) + ((lane & 16) >> 1);   // Q (B, non-trans)
    const unsigned qcol = (lane & 8) >> 1;                 // 0 or 4 words
    const int vrowrel = (lane & 7) + (lane & 8);           // V (B, trans)
    const unsigned vcol = (lane & 16) >> 2;                // 0 or 4 words

    float m0 = NEGF, m1 = NEGF, l0 = 0.f, l1 = 0.f;
    float acc[8][4];
#pragma unroll
    for (int nb = 0; nb < 8; nb++)
#pragma unroll
        for (int r = 0; r < 4; r++) acc[nb][r] = 0.f;

    const int jr0 = j0 + (warp << 4) + gid, jr1 = jr0 + 8;

    for (int it = 0; it < ntiles; ++it) {
        CP_WAIT1();
        __syncthreads();
        const unsigned stw = (it & 1) * STW;

        // ---- scores: m=j(16/warp), n=i(32), k=c(64) ----
        float s[4][4];
#pragma unroll
        for (int nb = 0; nb < 4; nb++)
#pragma unroll
            for (int r = 0; r < 4; r++) s[nb][r] = 0.f;
#pragma unroll
        for (int ks = 0; ks < 4; ks++) {
#pragma unroll
            for (int nbp = 0; nbp < 2; nbp++) {
                const unsigned qa = sbase +
                    ((stw + ((nbp << 4) + qrowrel) * RS + (ks << 3) + qcol) << 2);
                unsigned q0, q1, q2, q3, w0, w1, w2, w3;
                ldsm_x4(q0, q1, q2, q3, qa);
                ldsm_x4(w0, w1, w2, w3, qa + (1152 << 2));
                unsigned bh0[2] = {q0, q1}, bh1[2] = {q2, q3};
                unsigned bl0[2] = {w0, w1}, bl1[2] = {w2, w3};
                mma16(s[2*nbp],     kfl[ks], bh0);
                mma16(s[2*nbp],     kfh[ks], bl0);
                mma16(s[2*nbp],     kfh[ks], bh0);
                mma16(s[2*nbp + 1], kfl[ks], bh1);
                mma16(s[2*nbp + 1], kfh[ks], bl1);
                mma16(s[2*nbp + 1], kfh[ks], bh1);
            }
        }

        // ---- causal mask (last two tiles cover the diagonal 64-block) ----
        if (it >= ntiles - 2) {
            const int i0 = it << 5;
#pragma unroll
            for (int nb = 0; nb < 4; nb++) {
                const int c = i0 + (nb << 3) + (tig << 1);
                if (c     > jr0) s[nb][0] = NEGF;
                if (c + 1 > jr0) s[nb][1] = NEGF;
                if (c     > jr1) s[nb][2] = NEGF;
                if (c + 1 > jr1) s[nb][3] = NEGF;
            }
        }

        // ---- online softmax (rows jr0, jr1) ----
        float mt0 = NEGF, mt1 = NEGF;
#pragma unroll
        for (int nb = 0; nb < 4; nb++) {
            mt0 = fmaxf(mt0, fmaxf(s[nb][0], s[nb][1]));
            mt1 = fmaxf(mt1, fmaxf(s[nb][2], s[nb][3]));
        }
        mt0 = fmaxf(mt0, __shfl_xor_sync(0xffffffffu, mt0, 1));
        mt0 = fmaxf(mt0, __shfl_xor_sync(0xffffffffu, mt0, 2));
        mt1 = fmaxf(mt1, __shfl_xor_sync(0xffffffffu, mt1, 1));
        mt1 = fmaxf(mt1, __shfl_xor_sync(0xffffffffu, mt1, 2));
        const float mn0 = fmaxf(m0, mt0), mn1 = fmaxf(m1, mt1);
        const float sc0 = __expf(m0 - mn0), sc1 = __expf(m1 - mn1);
        m0 = mn0; m1 = mn1;

        float rs0 = 0.f, rs1 = 0.f;
#pragma unroll
        for (int nb = 0; nb < 4; nb++) {
            s[nb][0] = __expf(s[nb][0] - mn0);
            s[nb][1] = __expf(s[nb][1] - mn0);
            s[nb][2] = __expf(s[nb][2] - mn1);
            s[nb][3] = __expf(s[nb][3] - mn1);
            rs0 += s[nb][0] + s[nb][1];
            rs1 += s[nb][2] + s[nb][3];
        }
        rs0 += __shfl_xor_sync(0xffffffffu, rs0, 1);
        rs0 += __shfl_xor_sync(0xffffffffu, rs0, 2);
        rs1 += __shfl_xor_sync(0xffffffffu, rs1, 1);
        rs1 += __shfl_xor_sync(0xffffffffu, rs1, 2);
        l0 = l0 * sc0 + rs0;
        l1 = l1 * sc1 + rs1;

#pragma unroll
        for (int nb = 0; nb < 8; nb++) {
            acc[nb][0] *= sc0; acc[nb][1] *= sc0;
            acc[nb][2] *= sc1; acc[nb][3] *= sc1;
        }

        // ---- PV: m=j(16/warp), n=c(64), k=i(32); P from registers ----
#pragma unroll
        for (int kk = 0; kk < 2; kk++) {
            unsigned pah[4], pal[4];
            hl2(s[2*kk][0],     s[2*kk][1],     pah[0], pal[0]);
            hl2(s[2*kk][2],     s[2*kk][3],     pah[1], pal[1]);
            hl2(s[2*kk + 1][0], s[2*kk + 1][1], pah[2], pal[2]);
            hl2(s[2*kk + 1][2], s[2*kk + 1][3], pah[3], pal[3]);
#pragma unroll
            for (int nbp = 0; nbp < 4; nbp++) {
                const unsigned va = sbase +
                    ((stw + 2304 + ((kk << 4) + vrowrel) * RS + (nbp << 3) + vcol) << 2);
                unsigned v0, v1, v2, v3, w0, w1, w2, w3;
                ldsm_x4t(v0, v1, v2, v3, va);
                ldsm_x4t(w0, w1, w2, w3, va + (1152 << 2));
                unsigned vb0[2] = {v0, v1}, vb1[2] = {v2, v3};
                unsigned wb0[2] = {w0, w1}, wb1[2] = {w2, w3};
                mma16(acc[2*nbp],     pal, vb0);
                mma16(acc[2*nbp],     pah, wb0);
                mma16(acc[2*nbp],     pah, vb0);
                mma16(acc[2*nbp + 1], pal, vb1);
                mma16(acc[2*nbp + 1], pah, wb1);
                mma16(acc[2*nbp + 1], pah, vb1);
            }
        }

        __syncthreads();
        if (it + 2 < ntiles) LOADQV((it + 2) << 5, it & 1);
        CP_COMMIT();
    }

    // ---- epilogue: /l, pack, store ----
    const float rl0 = 1.0f / l0, rl1 = 1.0f / l1;
    const size_t o1 = ((rowb + jr0) << 8) + coff2;
    const size_t o2 = ((rowb + jr1) << 8) + coff2;
#pragma unroll
    for (int nb = 0; nb < 8; nb++) {
        const int pp = (nb << 2) + tig;
        unsigned H, L;
        hl2(acc[nb][0] * rl0, acc[nb][1] * rl0, H, L);
        aoh[o1 + pp] = H; aol[o1 + pp] = L;
        hl2(acc[nb][2] * rl1, acc[nb][3] * rl1, H, L);
        aoh[o2 + pp] = H; aol[o2 + pp] = L;
    }
#undef LOADQV
}

// ---------------- kernel 4: LN2 + transpose to (B,D,S) output ----------------
__global__ __launch_bounds__(128) void k_ln2(
    const float* __restrict__ res, const float* __restrict__ g2,
    const float* __restrict__ b2, float* __restrict__ out)
{
    const int bs = blockIdx.x;
    const int b = bs >> 10, s = bs & 1023;
    const int t = threadIdx.x;
    float x[4]; float ls1 = 0.f, ls2 = 0.f;
#pragma unroll
    for (int r = 0; r < 4; r++) {
        x[r] = res[((size_t)bs << 9) + t + (r << 7)];
        ls1 += x[r]; ls2 += x[r] * x[r];
    }
    __shared__ float sa[4], sb[4];
#pragma unroll
    for (int o = 16; o; o >>= 1) {
        ls1 += __shfl_down_sync(0xffffffffu, ls1, o);
        ls2 += __shfl_down_sync(0xffffffffu, ls2, o);
    }
    if ((t & 31) == 0) { sa[t >> 5] = ls1; sb[t >> 5] = ls2; }
    __syncthreads();
    const float S1 = sa[0] + sa[1] + sa[2] + sa[3];
    const float S2 = sb[0] + sb[1] + sb[2] + sb[3];
    const float mean = S1 * (1.0f / 512.0f);
    const float var  = (S2 - 512.0f * mean * mean) * (1.0f / 511.0f);
    const float rstd = rsqrtf(var + 1e-5f);
    const float gg = g2[s], be = b2[s];
#pragma unroll
    for (int r = 0; r < 4; r++) {
        const int d = t + (r << 7);
        out[((size_t)((b << 9) + d) << 10) + s] = gg * (x[r] - mean) * rstd + be;
    }
}

// ---------------- launch -----------------------------------------------------
extern "C" void kernel_launch(void* const* d_in, const int* in_sizes, int n_in,
                              void* d_out, int out_size)
{
    const float* ts     = (const float*)d_in[0];
    const int*   te     = (const int*)  d_in[1];
    const float* conv_w = (const float*)d_in[2];
    const float* conv_b = (const float*)d_in[3];
    const float* pe     = (const float*)d_in[4];
    const float* ts_emb = (const float*)d_in[5];
    const float* g1     = (const float*)d_in[6];
    const float* b1     = (const float*)d_in[7];
    const float* Mw     = (const float*)d_in[8];
    const float* Wq     = (const float*)d_in[9];
    const float* Wk     = (const float*)d_in[10];
    const float* Wv     = (const float*)d_in[11];
    const float* Wo     = (const float*)d_in[12];
    const float* bo     = (const float*)d_in[13];
    const float* g2     = (const float*)d_in[14];
    const float* b2     = (const float*)d_in[15];
    float* out = (float*)d_out;

    float *pc, *pr;
    unsigned *n1h, *n1l, *dh, *dl, *pqh, *pql, *pkh, *pkl, *pvh, *pvl, *ah, *al;
    unsigned *wmh, *wml, *wqh, *wql, *wkh, *wkl, *wvh, *wvl, *woh, *wol;
    cudaGetSymbolAddress((void**)&pc,  g_conv);
    cudaGetSymbolAddress((void**)&pr,  g_res);
    cudaGetSymbolAddress((void**)&n1h, g_n1h); cudaGetSymbolAddress((void**)&n1l, g_n1l);
    cudaGetSymbolAddress((void**)&dh,  g_dh);  cudaGetSymbolAddress((void**)&dl,  g_dl);
    cudaGetSymbolAddress((void**)&pqh, g_qh);  cudaGetSymbolAddress((void**)&pql, g_ql);
    cudaGetSymbolAddress((void**)&pkh, g_kh);  cudaGetSymbolAddress((void**)&pkl, g_kl);
    cudaGetSymbolAddress((void**)&pvh, g_vh);  cudaGetSymbolAddress((void**)&pvl, g_vl);
    cudaGetSymbolAddress((void**)&ah,  g_ah);  cudaGetSymbolAddress((void**)&al,  g_al);
    cudaGetSymbolAddress((void**)&wmh, g_wmh); cudaGetSymbolAddress((void**)&wml, g_wml);
    cudaGetSymbolAddress((void**)&wqh, g_wqh); cudaGetSymbolAddress((void**)&wql, g_wql);
    cudaGetSymbolAddress((void**)&wkh, g_wkh); cudaGetSymbolAddress((void**)&wkl, g_wkl);
    cudaGetSymbolAddress((void**)&wvh, g_wvh); cudaGetSymbolAddress((void**)&wvl, g_wvl);
    cudaGetSymbolAddress((void**)&woh, g_woh); cudaGetSymbolAddress((void**)&wol, g_wol);

    // weight packing (once per launch)
    const int n4 = DDIM * DDIM / 4;
    CvtTab tab;
    tab.in[0] = (const float4*)Mw; tab.oh[0] = (uint2*)wmh; tab.ol[0] = (uint2*)wml;
    tab.in[1] = (const float4*)Wq; tab.oh[1] = (uint2*)wqh; tab.ol[1] = (uint2*)wql;
    tab.in[2] = (const float4*)Wk; tab.oh[2] = (uint2*)wkh; tab.ol[2] = (uint2*)wkl;
    tab.in[3] = (const float4*)Wv; tab.oh[3] = (uint2*)wvh; tab.ol[3] = (uint2*)wvl;
    tab.in[4] = (const float4*)Wo; tab.oh[4] = (uint2*)woh; tab.ol[4] = (uint2*)wol;
    k_cvt5<<<dim3(n4 / 256, 5), 256>>>(tab, n4);

    k_embed<<<BSN, 128>>>(ts, conv_w, conv_b, pe, g1, b1, pc, n1h, n1l);

    dim3 gg(4, 128, 1);
    bf16_gemm<<<gg, 256>>>(n1h, n1l, wmh, wml, nullptr, nullptr, nullptr, nullptr,
                           dh, dl, nullptr, nullptr, nullptr, nullptr,
                           nullptr, 0, te, ts_emb, nullptr);
    dim3 gq(4, 128, 3);
    bf16_gemm<<<gq, 256>>>(dh, dl, wqh, wql, wkh, wkl, wvh, wvl,
                           pqh, pql, pkh, pkl, pvh, pvl,
                           nullptr, 4, nullptr, nullptr, nullptr);

    k_attn5<<<dim3(SSZ / 64, 8, BB), 128>>>(pqh, pql, pkh, pkl, pvh, pvl, ah, al);

    bf16_gemm<<<gg, 256>>>(ah, al, woh, wol, nullptr, nullptr, nullptr, nullptr,
                           nullptr, nullptr, nullptr, nullptr, nullptr, nullptr,
                           pr, 3, nullptr, bo, pc);

    k_ln2<<<BSN, 128>>>(pr, g2, b2, out);
}

// round 8
// speedup vs baseline: 2.9910x; 1.1083x over previous
#include <cuda_runtime.h>
#include <cuda_bf16.h>
#include <math.h>

#define BB   16
#define SSZ  1024
#define DDIM 512
#define PDIM 256            // packed pairs per row
#define BSN  (BB*SSZ)       // 16384 rows
#define NEGF (-1e30f)

// ---------------- scratch (device globals: allocation-free) ----------------
__device__ float    g_conv [BSN*DDIM];
__device__ float    g_res  [BSN*DDIM];
__device__ unsigned g_n1h[BSN*PDIM], g_n1l[BSN*PDIM];
__device__ unsigned g_dh [BSN*PDIM], g_dl [BSN*PDIM];
__device__ unsigned g_qh [BSN*PDIM], g_ql [BSN*PDIM];
__device__ unsigned g_kh [BSN*PDIM], g_kl [BSN*PDIM];
__device__ unsigned g_vh [BSN*PDIM], g_vl [BSN*PDIM];
__device__ unsigned g_ah [BSN*PDIM], g_al [BSN*PDIM];
__device__ unsigned g_wmh[DDIM*PDIM], g_wml[DDIM*PDIM];
__device__ unsigned g_wqh[DDIM*PDIM], g_wql[DDIM*PDIM];
__device__ unsigned g_wkh[DDIM*PDIM], g_wkl[DDIM*PDIM];
__device__ unsigned g_wvh[DDIM*PDIM], g_wvl[DDIM*PDIM];
__device__ unsigned g_woh[DDIM*PDIM], g_wol[DDIM*PDIM];

// ---------------- helpers ----------------------------------------------------
__device__ __forceinline__ unsigned short bfu(float x) {
    __nv_bfloat16 b = __float2bfloat16_rn(x);
    return *(unsigned short*)&b;
}
__device__ __forceinline__ float bff(unsigned short u) {
    __nv_bfloat16 b = *(__nv_bfloat16*)&u;
    return __bfloat162float(b);
}
__device__ __forceinline__ void hl2(float x0, float x1, unsigned& H, unsigned& L) {
    const unsigned short h0 = bfu(x0), h1 = bfu(x1);
    const unsigned short l0 = bfu(x0 - bff(h0)), l1 = bfu(x1 - bff(h1));
    H = (unsigned)h0 | ((unsigned)h1 << 16);
    L = (unsigned)l0 | ((unsigned)l1 << 16);
}
__device__ __forceinline__ void mma16(float* c, const unsigned* a, const unsigned* b) {
    asm volatile(
        "mma.sync.aligned.m16n8k16.row.col.f32.bf16.bf16.f32 "
        "{%0,%1,%2,%3}, {%4,%5,%6,%7}, {%8,%9}, {%0,%1,%2,%3};\n"
        : "+f"(c[0]), "+f"(c[1]), "+f"(c[2]), "+f"(c[3])
        : "r"(a[0]), "r"(a[1]), "r"(a[2]), "r"(a[3]), "r"(b[0]), "r"(b[1]));
}
__device__ __forceinline__ void ldsm_x4(unsigned& r0, unsigned& r1, unsigned& r2,
                                        unsigned& r3, unsigned addr) {
    asm volatile("ldmatrix.sync.aligned.m8n8.x4.shared.b16 {%0,%1,%2,%3}, [%4];"
        : "=r"(r0), "=r"(r1), "=r"(r2), "=r"(r3) : "r"(addr));
}
__device__ __forceinline__ void ldsm_x4t(unsigned& r0, unsigned& r1, unsigned& r2,
                                         unsigned& r3, unsigned addr) {
    asm volatile("ldmatrix.sync.aligned.m8n8.x4.trans.shared.b16 {%0,%1,%2,%3}, [%4];"
        : "=r"(r0), "=r"(r1), "=r"(r2), "=r"(r3) : "r"(addr));
}
__device__ __forceinline__ unsigned su32(const void* p) {
    return (unsigned)__cvta_generic_to_shared(p);
}
#define CP16(d, s) asm volatile("cp.async.cg.shared.global [%0], [%1], 16;\n" :: "r"(d), "l"(s))
#define CP_COMMIT()  asm volatile("cp.async.commit_group;\n")
#define CP_WAIT1()   asm volatile("cp.async.wait_group 1;\n")

// ---------------- kernel: fp32 -> packed bf16 (hi, lo) for 5 weights ---------
struct CvtTab { const float4* in[5]; uint2* oh[5]; uint2* ol[5]; };
__global__ __launch_bounds__(256) void k_cvt5(CvtTab tab, int n4)
{
    const int w = blockIdx.y;
    int i = blockIdx.x * 256 + threadIdx.x;
    if (i >= n4) return;
    float4 v = tab.in[w][i];
    unsigned h0, l0, h1, l1;
    hl2(v.x, v.y, h0, l0);
    hl2(v.z, v.w, h1, l1);
    tab.oh[w][i] = make_uint2(h0, h1);
    tab.ol[w][i] = make_uint2(l0, l1);
}

// ---------------- kernel 1: conv + pe + gelu + LN1 (packed hi/lo out) --------
__global__ __launch_bounds__(128) void k_embed(
    const float* __restrict__ ts, const float* __restrict__ cw,
    const float* __restrict__ cb, const float* __restrict__ pe,
    const float* __restrict__ g1, const float* __restrict__ b1,
    float* __restrict__ convo, unsigned* __restrict__ n1h, unsigned* __restrict__ n1l)
{
    const int bs = blockIdx.x;
    const int b = bs >> 10, s = bs & 1023;
    const int t = threadIdx.x;
    const int d0 = t << 2;
    const float* tp = ts + ((size_t)b << 12) + (s << 2);
    const float t0 = tp[0], t1 = tp[1], t2 = tp[2], t3 = tp[3];

    const float4 cb4 = *(const float4*)(cb + d0);
    const float4 pe4 = *(const float4*)(pe + ((size_t)s << 9) + d0);

    float cvv[4], act[4];
    float ls1 = 0.f, ls2 = 0.f;
#pragma unroll
    for (int j = 0; j < 4; j++) {
        const float4 w = *(const float4*)(cw + ((d0 + j) << 2));
        float c = fmaf(t0, w.x, fmaf(t1, w.y, fmaf(t2, w.z, t3 * w.w)));
        c += ((const float*)&cb4)[j] + ((const float*)&pe4)[j];
        cvv[j] = c;
        const float a = 0.5f * c * (1.0f + erff(c * 0.70710678118654752f));
        act[j] = a; ls1 += a; ls2 += a * a;
    }
    *(float4*)(convo + ((size_t)bs << 9) + d0) = make_float4(cvv[0], cvv[1], cvv[2], cvv[3]);

    __shared__ float sa[4], sb[4];
#pragma unroll
    for (int o = 16; o; o >>= 1) {
        ls1 += __shfl_down_sync(0xffffffffu, ls1, o);
        ls2 += __shfl_down_sync(0xffffffffu, ls2, o);
    }
    if ((t & 31) == 0) { sa[t >> 5] = ls1; sb[t >> 5] = ls2; }
    __syncthreads();
    const float S1 = sa[0] + sa[1] + sa[2] + sa[3];
    const float S2 = sb[0] + sb[1] + sb[2] + sb[3];
    const float mean = S1 * (1.0f / 512.0f);
    const float var  = (S2 - 512.0f * mean * mean) * (1.0f / 511.0f);  // ddof=1
    const float rstd = rsqrtf(var + 1e-5f);
    const float gg = g1[s], be = b1[s];

    float v[4];
#pragma unroll
    for (int j = 0; j < 4; j++) v[j] = gg * (act[j] - mean) * rstd + be;
    unsigned H0, L0, H1, L1;
    hl2(v[0], v[1], H0, L0);
    hl2(v[2], v[3], H1, L1);
    const size_t pr = ((size_t)bs << 8) + (t << 1);
    *(uint2*)(n1h + pr) = make_uint2(H0, H1);
    *(uint2*)(n1l + pr) = make_uint2(L0, L1);
}

// ---------------- BF16x3 GEMM-NT, ldmatrix fragment loads --------------------
#define SP2 12               // smem row stride in pairs (8 data + 4 pad)
#define GARR 1536            // words per array per stage (128*12)
#define GST  (4*GARR)        // 6144 words per stage
__global__ __launch_bounds__(256, 2) void bf16_gemm(
    const unsigned* __restrict__ Agh, const unsigned* __restrict__ Agl,
    const unsigned* __restrict__ B0h, const unsigned* __restrict__ B0l,
    const unsigned* __restrict__ B1h, const unsigned* __restrict__ B1l,
    const unsigned* __restrict__ B2h, const unsigned* __restrict__ B2l,
    unsigned* __restrict__ C0h, unsigned* __restrict__ C0l,
    unsigned* __restrict__ C1h, unsigned* __restrict__ C1l,
    unsigned* __restrict__ C2h, unsigned* __restrict__ C2l,
    float* __restrict__ Cf, int mode, const int* __restrict__ te,
    const float* __restrict__ aux1, const float* __restrict__ aux2)
{
    __shared__ unsigned gsm[2 * GST];            // 49152 B static

    const unsigned* Bgh = B0h; const unsigned* Bgl = B0l;
    unsigned* Ch = C0h; unsigned* Cl = C0l;
    float scale = 1.0f;
    if (mode == 4) {
        if (blockIdx.z == 1)      { Bgh = B1h; Bgl = B1l; Ch = C1h; Cl = C1l; }
        else if (blockIdx.z == 2) { Bgh = B2h; Bgl = B2l; Ch = C2h; Cl = C2l; }
        else                      { scale = 0.125f; }
    }

    const int t = threadIdx.x;
    const int row0 = blockIdx.y << 7, col0 = blockIdx.x << 7;
    const int lrow = t >> 1, lchunk = t & 1;
    const size_t aoff = ((size_t)(row0 + lrow) << 8) + (lchunk << 2);
    const size_t boff = ((size_t)(col0 + lrow) << 8) + (lchunk << 2);
    const unsigned cta = su32(gsm);
    const unsigned sbase = cta + (unsigned)((lrow * SP2 + (lchunk << 2)) << 2);

    const int warp = t >> 5, lane = t & 31;
    const int gid = lane >> 2, tig = lane & 3;
    const int wm = warp & 1, wn = warp >> 1;

    // ldmatrix address components
    // A (m16, A-fragment): lanes 0-15 -> rows 0-15 k-half 0; lanes 16-31 -> +16B
    const int arowr = (wm << 6) + (lane & 15);
    const unsigned acolB = (unsigned)(lane & 16);          // 0 or 16 bytes
    // B (two n8 tiles): lanes 0-7 rows(nt0)+0B; 8-15 rows(nt0)+16B;
    //                   16-23 rows(nt1)+0B; 24-31 rows(nt1)+16B
    const int browr = (wn << 5) + (lane & 7) + (((lane >> 4) & 1) << 3);
    const unsigned bcolB = (unsigned)(((lane >> 3) & 1) << 4);

    float acc[4][4][4];
#pragma unroll
    for (int mt = 0; mt < 4; mt++)
#pragma unroll
        for (int nt = 0; nt < 4; nt++)
#pragma unroll
            for (int r = 0; r < 4; r++) acc[mt][nt][r] = 0.f;

#define GLOAD(kt, st) do {                                   \
        const unsigned kc = (unsigned)(kt) << 3;             \
        const unsigned sd = sbase + (st) * (GST << 2);       \
        CP16(sd,                 Agh + aoff + kc);           \
        CP16(sd + (GARR << 2),   Agl + aoff + kc);           \
        CP16(sd + (2*GARR << 2), Bgh + boff + kc);           \
        CP16(sd + (3*GARR << 2), Bgl + boff + kc);           \
    } while (0)

    GLOAD(0, 0); CP_COMMIT();
    GLOAD(1, 1); CP_COMMIT();

    for (int kt = 0; kt < 32; kt++) {
        CP_WAIT1();
        __syncthreads();
        const unsigned stB = cta + (kt & 1) * (GST << 2);

        unsigned bh[4][2], bl[4][2];
#pragma unroll
        for (int ntp = 0; ntp < 2; ntp++) {
            const unsigned ba = stB +
                (((2*GARR) + (browr + (ntp << 4)) * SP2) << 2) + bcolB;
            ldsm_x4(bh[2*ntp][0], bh[2*ntp][1], bh[2*ntp+1][0], bh[2*ntp+1][1], ba);
            ldsm_x4(bl[2*ntp][0], bl[2*ntp][1], bl[2*ntp+1][0], bl[2*ntp+1][1],
                    ba + (GARR << 2));
        }
#pragma unroll
        for (int mt = 0; mt < 4; mt++) {
            const unsigned aa = stB + (((arowr + (mt << 4)) * SP2) << 2) + acolB;
            unsigned ah[4], al[4];
            ldsm_x4(ah[0], ah[1], ah[2], ah[3], aa);
            ldsm_x4(al[0], al[1], al[2], al[3], aa + (GARR << 2));
#pragma unroll
            for (int nt = 0; nt < 4; nt++) {
                mma16(acc[mt][nt], al, bh[nt]);
                mma16(acc[mt][nt], ah, bl[nt]);
                mma16(acc[mt][nt], ah, bh[nt]);
            }
        }
        __syncthreads();
        if (kt + 2 < 32) GLOAD(kt + 2, kt & 1);
        CP_COMMIT();
    }

    // ---- epilogue ----
    if (mode == 3) {
#pragma unroll
        for (int mt = 0; mt < 4; mt++) {
            const int r1 = row0 + (wm << 6) + (mt << 4) + gid;
            const int r2 = r1 + 8;
#pragma unroll
            for (int nt = 0; nt < 4; nt++) {
                const int c = col0 + (wn << 5) + (nt << 3) + (tig << 1);
                const float a0 = aux1[c], a1 = aux1[c + 1];
                float v0 = acc[mt][nt][0] + a0 + aux2[((size_t)r1 << 9) + c];
                float v1 = acc[mt][nt][1] + a1 + aux2[((size_t)r1 << 9) + c + 1];
                float v2 = acc[mt][nt][2] + a0 + aux2[((size_t)r2 << 9) + c];
                float v3 = acc[mt][nt][3] + a1 + aux2[((size_t)r2 << 9) + c + 1];
                *(float2*)(Cf + ((size_t)r1 << 9) + c) = make_float2(v0, v1);
                *(float2*)(Cf + ((size_t)r2 << 9) + c) = make_float2(v2, v3);
            }
        }
    } else {
        int e = 0;
        if (mode == 0) e = te[row0 >> 10];
#pragma unroll
        for (int mt = 0; mt < 4; mt++) {
            const int r1 = row0 + (wm << 6) + (mt << 4) + gid;
            const int r2 = r1 + 8;
#pragma unroll
            for (int nt = 0; nt < 4; nt++) {
                const int c = col0 + (wn << 5) + (nt << 3) + (tig << 1);
                float a0 = 0.f, a1 = 0.f;
                if (mode == 0) {
                    a0 = aux1[((size_t)e << 9) + c];
                    a1 = aux1[((size_t)e << 9) + c + 1];
                }
                const float v0 = acc[mt][nt][0] * scale + a0;
                const float v1 = acc[mt][nt][1] * scale + a1;
                const float v2 = acc[mt][nt][2] * scale + a0;
                const float v3 = acc[mt][nt][3] * scale + a1;
                unsigned H, L;
                const size_t i0p = ((size_t)r1 << 8) + (c >> 1);
                const size_t i1p = ((size_t)r2 << 8) + (c >> 1);
                hl2(v0, v1, H, L); Ch[i0p] = H; Cl[i0p] = L;
                hl2(v2, v3, H, L); Ch[i1p] = H; Cl[i1p] = L;
            }
        }
    }
}

// ---------------- FA2-style bf16x3 attention, static 36KB smem ---------------
// (unchanged from round 7 — proven at ~200us)
#define RS 36
#define STW 4608
__global__ __launch_bounds__(128, 2) void k_attn5(
    const unsigned* __restrict__ qh, const unsigned* __restrict__ ql,
    const unsigned* __restrict__ kh, const unsigned* __restrict__ kl,
    const unsigned* __restrict__ vh, const unsigned* __restrict__ vl,
    unsigned* __restrict__ aoh, unsigned* __restrict__ aol)
{
    __shared__ unsigned smw[2 * STW];            // 36864 B static

    const int jt = (gridDim.x - 1) - blockIdx.x; // big tiles first
    const int h = blockIdx.y, b = blockIdx.z;
    const int j0 = jt << 6;
    const int t = threadIdx.x, warp = t >> 5, lane = t & 31;
    const int gid = lane >> 2, tig = lane & 3;
    const size_t rowb = ((size_t)b << 10);
    const int coff2 = h << 5;
    const unsigned sbase = su32(smw);

    const int lrow = t >> 2;                     // 0..31
    const int lsub = (t & 3) << 3;               // word offset 0,8,16,24

#define LOADQV(i0_, st_) do {                                                   \
        const size_t g_ = ((rowb + (unsigned)(i0_) + lrow) << 8) + coff2 + lsub; \
        const unsigned s_ = sbase + (((st_) * STW + lrow * RS + lsub) << 2);     \
        CP16(s_,                  qh + g_);                                     \
        CP16(s_ + 16,             qh + g_ + 4);                                 \
        CP16(s_ + (1152 << 2),      ql + g_);                                   \
        CP16(s_ + (1152 << 2) + 16, ql + g_ + 4);                               \
        CP16(s_ + (2304 << 2),      vh + g_);                                   \
        CP16(s_ + (2304 << 2) + 16, vh + g_ + 4);                               \
        CP16(s_ + (3456 << 2),      vl + g_);                                   \
        CP16(s_ + (3456 << 2) + 16, vl + g_ + 4);                               \
    } while (0)

    const int ntiles = (jt << 1) + 2;

    LOADQV(0, 0); CP_COMMIT();
    if (ntiles > 1) LOADQV(32, 1);
    CP_COMMIT();

    const int krow = j0 + (warp << 4) + gid;
    const size_t kg0 = ((rowb + krow) << 8) + coff2;
    const size_t kg8 = ((rowb + krow + 8) << 8) + coff2;
    unsigned kfh[4][4], kfl[4][4];
#pragma unroll
    for (int ks = 0; ks < 4; ks++) {
        const int p = (ks << 3) + tig;
        kfh[ks][0] = kh[kg0 + p];     kfh[ks][1] = kh[kg8 + p];
        kfh[ks][2] = kh[kg0 + p + 4]; kfh[ks][3] = kh[kg8 + p + 4];
        kfl[ks][0] = kl[kg0 + p];     kfl[ks][1] = kl[kg8 + p];
        kfl[ks][2] = kl[kg0 + p + 4]; kfl[ks][3] = kl[kg8 + p + 4];
    }

    const int qrowrel = (lane & 7) + ((lane & 16) >> 1);
    const unsigned qcol = (lane & 8) >> 1;
    const int vrowrel = (lane & 7) + (lane & 8);
    const unsigned vcol = (lane & 16) >> 2;

    float m0 = NEGF, m1 = NEGF, l0 = 0.f, l1 = 0.f;
    float acc[8][4];
#pragma unroll
    for (int nb = 0; nb < 8; nb++)
#pragma unroll
        for (int r = 0; r < 4; r++) acc[nb][r] = 0.f;

    const int jr0 = j0 + (warp << 4) + gid, jr1 = jr0 + 8;

    for (int it = 0; it < ntiles; ++it) {
        CP_WAIT1();
        __syncthreads();
        const unsigned stw = (it & 1) * STW;

        float s[4][4];
#pragma unroll
        for (int nb = 0; nb < 4; nb++)
#pragma unroll
            for (int r = 0; r < 4; r++) s[nb][r] = 0.f;
#pragma unroll
        for (int ks = 0; ks < 4; ks++) {
#pragma unroll
            for (int nbp = 0; nbp < 2; nbp++) {
                const unsigned qa = sbase +
                    ((stw + ((nbp << 4) + qrowrel) * RS + (ks << 3) + qcol) << 2);
                unsigned q0, q1, q2, q3, w0, w1, w2, w3;
                ldsm_x4(q0, q1, q2, q3, qa);
                ldsm_x4(w0, w1, w2, w3, qa + (1152 << 2));
                unsigned bh0[2] = {q0, q1}, bh1[2] = {q2, q3};
                unsigned bl0[2] = {w0, w1}, bl1[2] = {w2, w3};
                mma16(s[2*nbp],     kfl[ks], bh0);
                mma16(s[2*nbp],     kfh[ks], bl0);
                mma16(s[2*nbp],     kfh[ks], bh0);
                mma16(s[2*nbp + 1], kfl[ks], bh1);
                mma16(s[2*nbp + 1], kfh[ks], bl1);
                mma16(s[2*nbp + 1], kfh[ks], bh1);
            }
        }

        if (it >= ntiles - 2) {
            const int i0 = it << 5;
#pragma unroll
            for (int nb = 0; nb < 4; nb++) {
                const int c = i0 + (nb << 3) + (tig << 1);
                if (c     > jr0) s[nb][0] = NEGF;
                if (c + 1 > jr0) s[nb][1] = NEGF;
                if (c     > jr1) s[nb][2] = NEGF;
                if (c + 1 > jr1) s[nb][3] = NEGF;
            }
        }

        float mt0 = NEGF, mt1 = NEGF;
#pragma unroll
        for (int nb = 0; nb < 4; nb++) {
            mt0 = fmaxf(mt0, fmaxf(s[nb][0], s[nb][1]));
            mt1 = fmaxf(mt1, fmaxf(s[nb][2], s[nb][3]));
        }
        mt0 = fmaxf(mt0, __shfl_xor_sync(0xffffffffu, mt0, 1));
        mt0 = fmaxf(mt0, __shfl_xor_sync(0xffffffffu, mt0, 2));
        mt1 = fmaxf(mt1, __shfl_xor_sync(0xffffffffu, mt1, 1));
        mt1 = fmaxf(mt1, __shfl_xor_sync(0xffffffffu, mt1, 2));
        const float mn0 = fmaxf(m0, mt0), mn1 = fmaxf(m1, mt1);
        const float sc0 = __expf(m0 - mn0), sc1 = __expf(m1 - mn1);
        m0 = mn0; m1 = mn1;

        float rs0 = 0.f, rs1 = 0.f;
#pragma unroll
        for (int nb = 0; nb < 4; nb++) {
            s[nb][0] = __expf(s[nb][0] - mn0);
            s[nb][1] = __expf(s[nb][1] - mn0);
            s[nb][2] = __expf(s[nb][2] - mn1);
            s[nb][3] = __expf(s[nb][3] - mn1);
            rs0 += s[nb][0] + s[nb][1];
            rs1 += s[nb][2] + s[nb][3];
        }
        rs0 += __shfl_xor_sync(0xffffffffu, rs0, 1);
        rs0 += __shfl_xor_sync(0xffffffffu, rs0, 2);
        rs1 += __shfl_xor_sync(0xffffffffu, rs1, 1);
        rs1 += __shfl_xor_sync(0xffffffffu, rs1, 2);
        l0 = l0 * sc0 + rs0;
        l1 = l1 * sc1 + rs1;

#pragma unroll
        for (int nb = 0; nb < 8; nb++) {
            acc[nb][0] *= sc0; acc[nb][1] *= sc0;
            acc[nb][2] *= sc1; acc[nb][3] *= sc1;
        }

#pragma unroll
        for (int kk = 0; kk < 2; kk++) {
            unsigned pah[4], pal[4];
            hl2(s[2*kk][0],     s[2*kk][1],     pah[0], pal[0]);
            hl2(s[2*kk][2],     s[2*kk][3],     pah[1], pal[1]);
            hl2(s[2*kk + 1][0], s[2*kk + 1][1], pah[2], pal[2]);
            hl2(s[2*kk + 1][2], s[2*kk + 1][3], pah[3], pal[3]);
#pragma unroll
            for (int nbp = 0; nbp < 4; nbp++) {
                const unsigned va = sbase +
                    ((stw + 2304 + ((kk << 4) + vrowrel) * RS + (nbp << 3) + vcol) << 2);
                unsigned v0, v1, v2, v3, w0, w1, w2, w3;
                ldsm_x4t(v0, v1, v2, v3, va);
                ldsm_x4t(w0, w1, w2, w3, va + (1152 << 2));
                unsigned vb0[2] = {v0, v1}, vb1[2] = {v2, v3};
                unsigned wb0[2] = {w0, w1}, wb1[2] = {w2, w3};
                mma16(acc[2*nbp],     pal, vb0);
                mma16(acc[2*nbp],     pah, wb0);
                mma16(acc[2*nbp],     pah, vb0);
                mma16(acc[2*nbp + 1], pal, vb1);
                mma16(acc[2*nbp + 1], pah, wb1);
                mma16(acc[2*nbp + 1], pah, vb1);
            }
        }

        __syncthreads();
        if (it + 2 < ntiles) LOADQV((it + 2) << 5, it & 1);
        CP_COMMIT();
    }

    const float rl0 = 1.0f / l0, rl1 = 1.0f / l1;
    const size_t o1 = ((rowb + jr0) << 8) + coff2;
    const size_t o2 = ((rowb + jr1) << 8) + coff2;
#pragma unroll
    for (int nb = 0; nb < 8; nb++) {
        const int pp = (nb << 2) + tig;
        unsigned H, L;
        hl2(acc[nb][0] * rl0, acc[nb][1] * rl0, H, L);
        aoh[o1 + pp] = H; aol[o1 + pp] = L;
        hl2(acc[nb][2] * rl1, acc[nb][3] * rl1, H, L);
        aoh[o2 + pp] = H; aol[o2 + pp] = L;
    }
#undef LOADQV
}

// ---------------- kernel 4: LN2 + transpose to (B,D,S) output ----------------
__global__ __launch_bounds__(128) void k_ln2(
    const float* __restrict__ res, const float* __restrict__ g2,
    const float* __restrict__ b2, float* __restrict__ out)
{
    const int bs = blockIdx.x;
    const int b = bs >> 10, s = bs & 1023;
    const int t = threadIdx.x;
    float x[4]; float ls1 = 0.f, ls2 = 0.f;
#pragma unroll
    for (int r = 0; r < 4; r++) {
        x[r] = res[((size_t)bs << 9) + t + (r << 7)];
        ls1 += x[r]; ls2 += x[r] * x[r];
    }
    __shared__ float sa[4], sb[4];
#pragma unroll
    for (int o = 16; o; o >>= 1) {
        ls1 += __shfl_down_sync(0xffffffffu, ls1, o);
        ls2 += __shfl_down_sync(0xffffffffu, ls2, o);
    }
    if ((t & 31) == 0) { sa[t >> 5] = ls1; sb[t >> 5] = ls2; }
    __syncthreads();
    const float S1 = sa[0] + sa[1] + sa[2] + sa[3];
    const float S2 = sb[0] + sb[1] + sb[2] + sb[3];
    const float mean = S1 * (1.0f / 512.0f);
    const float var  = (S2 - 512.0f * mean * mean) * (1.0f / 511.0f);
    const float rstd = rsqrtf(var + 1e-5f);
    const float gg = g2[s], be = b2[s];
#pragma unroll
    for (int r = 0; r < 4; r++) {
        const int d = t + (r << 7);
        out[((size_t)((b << 9) + d) << 10) + s] = gg * (x[r] - mean) * rstd + be;
    }
}

// ---------------- launch -----------------------------------------------------
extern "C" void kernel_launch(void* const* d_in, const int* in_sizes, int n_in,
                              void* d_out, int out_size)
{
    const float* ts     = (const float*)d_in[0];
    const int*   te     = (const int*)  d_in[1];
    const float* conv_w = (const float*)d_in[2];
    const float* conv_b = (const float*)d_in[3];
    const float* pe     = (const float*)d_in[4];
    const float* ts_emb = (const float*)d_in[5];
    const float* g1     = (const float*)d_in[6];
    const float* b1     = (const float*)d_in[7];
    const float* Mw     = (const float*)d_in[8];
    const float* Wq     = (const float*)d_in[9];
    const float* Wk     = (const float*)d_in[10];
    const float* Wv     = (const float*)d_in[11];
    const float* Wo     = (const float*)d_in[12];
    const float* bo     = (const float*)d_in[13];
    const float* g2     = (const float*)d_in[14];
    const float* b2     = (const float*)d_in[15];
    float* out = (float*)d_out;

    float *pc, *pr;
    unsigned *n1h, *n1l, *dh, *dl, *pqh, *pql, *pkh, *pkl, *pvh, *pvl, *ah, *al;
    unsigned *wmh, *wml, *wqh, *wql, *wkh, *wkl, *wvh, *wvl, *woh, *wol;
    cudaGetSymbolAddress((void**)&pc,  g_conv);
    cudaGetSymbolAddress((void**)&pr,  g_res);
    cudaGetSymbolAddress((void**)&n1h, g_n1h); cudaGetSymbolAddress((void**)&n1l, g_n1l);
    cudaGetSymbolAddress((void**)&dh,  g_dh);  cudaGetSymbolAddress((void**)&dl,  g_dl);
    cudaGetSymbolAddress((void**)&pqh, g_qh);  cudaGetSymbolAddress((void**)&pql, g_ql);
    cudaGetSymbolAddress((void**)&pkh, g_kh);  cudaGetSymbolAddress((void**)&pkl, g_kl);
    cudaGetSymbolAddress((void**)&pvh, g_vh);  cudaGetSymbolAddress((void**)&pvl, g_vl);
    cudaGetSymbolAddress((void**)&ah,  g_ah);  cudaGetSymbolAddress((void**)&al,  g_al);
    cudaGetSymbolAddress((void**)&wmh, g_wmh); cudaGetSymbolAddress((void**)&wml, g_wml);
    cudaGetSymbolAddress((void**)&wqh, g_wqh); cudaGetSymbolAddress((void**)&wql, g_wql);
    cudaGetSymbolAddress((void**)&wkh, g_wkh); cudaGetSymbolAddress((void**)&wkl, g_wkl);
    cudaGetSymbolAddress((void**)&wvh, g_wvh); cudaGetSymbolAddress((void**)&wvl, g_wvl);
    cudaGetSymbolAddress((void**)&woh, g_woh); cudaGetSymbolAddress((void**)&wol, g_wol);

    // weight packing (once per launch)
    const int n4 = DDIM * DDIM / 4;
    CvtTab tab;
    tab.in[0] = (const float4*)Mw; tab.oh[0] = (uint2*)wmh; tab.ol[0] = (uint2*)wml;
    tab.in[1] = (const float4*)Wq; tab.oh[1] = (uint2*)wqh; tab.ol[1] = (uint2*)wql;
    tab.in[2] = (const float4*)Wk; tab.oh[2] = (uint2*)wkh; tab.ol[2] = (uint2*)wkl;
    tab.in[3] = (const float4*)Wv; tab.oh[3] = (uint2*)wvh; tab.ol[3] = (uint2*)wvl;
    tab.in[4] = (const float4*)Wo; tab.oh[4] = (uint2*)woh; tab.ol[4] = (uint2*)wol;
    k_cvt5<<<dim3(n4 / 256, 5), 256>>>(tab, n4);

    k_embed<<<BSN, 128>>>(ts, conv_w, conv_b, pe, g1, b1, pc, n1h, n1l);

    dim3 gg(4, 128, 1);
    bf16_gemm<<<gg, 256>>>(n1h, n1l, wmh, wml, nullptr, nullptr, nullptr, nullptr,
                           dh, dl, nullptr, nullptr, nullptr, nullptr,
                           nullptr, 0, te, ts_emb, nullptr);
    dim3 gq(4, 128, 3);
    bf16_gemm<<<gq, 256>>>(dh, dl, wqh, wql, wkh, wkl, wvh, wvl,
                           pqh, pql, pkh, pkl, pvh, pvl,
                           nullptr, 4, nullptr, nullptr, nullptr);

    k_attn5<<<dim3(SSZ / 64, 8, BB), 128>>>(pqh, pql, pkh, pkl, pvh, pvl, ah, al);

    bf16_gemm<<<gg, 256>>>(ah, al, woh, wol, nullptr, nullptr, nullptr, nullptr,
                           nullptr, nullptr, nullptr, nullptr, nullptr, nullptr,
                           pr, 3, nullptr, bo, pc);

    k_ln2<<<BSN, 128>>>(pr, g2, b2, out);
}

// round 9
// speedup vs baseline: 3.1080x; 1.0391x over previous
#include <cuda_runtime.h>
#include <cuda_bf16.h>
#include <math.h>

#define BB   16
#define SSZ  1024
#define DDIM 512
#define PDIM 256            // packed pairs per row
#define BSN  (BB*SSZ)       // 16384 rows
#define NEGF (-1e30f)

// ---------------- scratch (device globals: allocation-free) ----------------
__device__ float    g_conv [BSN*DDIM];
__device__ float    g_res  [BSN*DDIM];
__device__ unsigned g_n1h[BSN*PDIM], g_n1l[BSN*PDIM];
__device__ unsigned g_dh [BSN*PDIM], g_dl [BSN*PDIM];
__device__ unsigned g_qh [BSN*PDIM], g_ql [BSN*PDIM];
__device__ unsigned g_kh [BSN*PDIM], g_kl [BSN*PDIM];
__device__ unsigned g_vh [BSN*PDIM], g_vl [BSN*PDIM];
__device__ unsigned g_ah [BSN*PDIM], g_al [BSN*PDIM];
__device__ unsigned g_wmh[DDIM*PDIM], g_wml[DDIM*PDIM];
__device__ unsigned g_wqh[DDIM*PDIM], g_wql[DDIM*PDIM];
__device__ unsigned g_wkh[DDIM*PDIM], g_wkl[DDIM*PDIM];
__device__ unsigned g_wvh[DDIM*PDIM], g_wvl[DDIM*PDIM];
__device__ unsigned g_woh[DDIM*PDIM], g_wol[DDIM*PDIM];

// ---------------- helpers ----------------------------------------------------
__device__ __forceinline__ unsigned short bfu(float x) {
    __nv_bfloat16 b = __float2bfloat16_rn(x);
    return *(unsigned short*)&b;
}
__device__ __forceinline__ float bff(unsigned short u) {
    __nv_bfloat16 b = *(__nv_bfloat16*)&u;
    return __bfloat162float(b);
}
__device__ __forceinline__ void hl2(float x0, float x1, unsigned& H, unsigned& L) {
    const unsigned short h0 = bfu(x0), h1 = bfu(x1);
    const unsigned short l0 = bfu(x0 - bff(h0)), l1 = bfu(x1 - bff(h1));
    H = (unsigned)h0 | ((unsigned)h1 << 16);
    L = (unsigned)l0 | ((unsigned)l1 << 16);
}
__device__ __forceinline__ void mma16(float* c, const unsigned* a, const unsigned* b) {
    asm volatile(
        "mma.sync.aligned.m16n8k16.row.col.f32.bf16.bf16.f32 "
        "{%0,%1,%2,%3}, {%4,%5,%6,%7}, {%8,%9}, {%0,%1,%2,%3};\n"
        : "+f"(c[0]), "+f"(c[1]), "+f"(c[2]), "+f"(c[3])
        : "r"(a[0]), "r"(a[1]), "r"(a[2]), "r"(a[3]), "r"(b[0]), "r"(b[1]));
}
__device__ __forceinline__ void ldsm_x4(unsigned& r0, unsigned& r1, unsigned& r2,
                                        unsigned& r3, unsigned addr) {
    asm volatile("ldmatrix.sync.aligned.m8n8.x4.shared.b16 {%0,%1,%2,%3}, [%4];"
        : "=r"(r0), "=r"(r1), "=r"(r2), "=r"(r3) : "r"(addr));
}
__device__ __forceinline__ void ldsm_x4t(unsigned& r0, unsigned& r1, unsigned& r2,
                                         unsigned& r3, unsigned addr) {
    asm volatile("ldmatrix.sync.aligned.m8n8.x4.trans.shared.b16 {%0,%1,%2,%3}, [%4];"
        : "=r"(r0), "=r"(r1), "=r"(r2), "=r"(r3) : "r"(addr));
}
__device__ __forceinline__ unsigned su32(const void* p) {
    return (unsigned)__cvta_generic_to_shared(p);
}
#define CP16(d, s) asm volatile("cp.async.cg.shared.global [%0], [%1], 16;\n" :: "r"(d), "l"(s))
#define CP_COMMIT()  asm volatile("cp.async.commit_group;\n")
#define CP_WAIT1()   asm volatile("cp.async.wait_group 1;\n")

// ---------------- kernel: fp32 -> packed bf16 (hi, lo) for 5 weights ---------
struct CvtTab { const float4* in[5]; uint2* oh[5]; uint2* ol[5]; };
__global__ __launch_bounds__(256) void k_cvt5(CvtTab tab, int n4)
{
    const int w = blockIdx.y;
    int i = blockIdx.x * 256 + threadIdx.x;
    if (i >= n4) return;
    float4 v = tab.in[w][i];
    unsigned h0, l0, h1, l1;
    hl2(v.x, v.y, h0, l0);
    hl2(v.z, v.w, h1, l1);
    tab.oh[w][i] = make_uint2(h0, h1);
    tab.ol[w][i] = make_uint2(l0, l1);
}

// ---------------- kernel 1: conv + pe + gelu + LN1 (packed hi/lo out) --------
__global__ __launch_bounds__(128) void k_embed(
    const float* __restrict__ ts, const float* __restrict__ cw,
    const float* __restrict__ cb, const float* __restrict__ pe,
    const float* __restrict__ g1, const float* __restrict__ b1,
    float* __restrict__ convo, unsigned* __restrict__ n1h, unsigned* __restrict__ n1l)
{
    const int bs = blockIdx.x;
    const int b = bs >> 10, s = bs & 1023;
    const int t = threadIdx.x;
    const int d0 = t << 2;
    const float* tp = ts + ((size_t)b << 12) + (s << 2);
    const float t0 = tp[0], t1 = tp[1], t2 = tp[2], t3 = tp[3];

    const float4 cb4 = *(const float4*)(cb + d0);
    const float4 pe4 = *(const float4*)(pe + ((size_t)s << 9) + d0);

    float cvv[4], act[4];
    float ls1 = 0.f, ls2 = 0.f;
#pragma unroll
    for (int j = 0; j < 4; j++) {
        const float4 w = *(const float4*)(cw + ((d0 + j) << 2));
        float c = fmaf(t0, w.x, fmaf(t1, w.y, fmaf(t2, w.z, t3 * w.w)));
        c += ((const float*)&cb4)[j] + ((const float*)&pe4)[j];
        cvv[j] = c;
        const float a = 0.5f * c * (1.0f + erff(c * 0.70710678118654752f));
        act[j] = a; ls1 += a; ls2 += a * a;
    }
    *(float4*)(convo + ((size_t)bs << 9) + d0) = make_float4(cvv[0], cvv[1], cvv[2], cvv[3]);

    __shared__ float sa[4], sb[4];
#pragma unroll
    for (int o = 16; o; o >>= 1) {
        ls1 += __shfl_down_sync(0xffffffffu, ls1, o);
        ls2 += __shfl_down_sync(0xffffffffu, ls2, o);
    }
    if ((t & 31) == 0) { sa[t >> 5] = ls1; sb[t >> 5] = ls2; }
    __syncthreads();
    const float S1 = sa[0] + sa[1] + sa[2] + sa[3];
    const float S2 = sb[0] + sb[1] + sb[2] + sb[3];
    const float mean = S1 * (1.0f / 512.0f);
    const float var  = (S2 - 512.0f * mean * mean) * (1.0f / 511.0f);  // ddof=1
    const float rstd = rsqrtf(var + 1e-5f);
    const float gg = g1[s], be = b1[s];

    float v[4];
#pragma unroll
    for (int j = 0; j < 4; j++) v[j] = gg * (act[j] - mean) * rstd + be;
    unsigned H0, L0, H1, L1;
    hl2(v[0], v[1], H0, L0);
    hl2(v[2], v[3], H1, L1);
    const size_t pr = ((size_t)bs << 8) + (t << 1);
    *(uint2*)(n1h + pr) = make_uint2(H0, H1);
    *(uint2*)(n1l + pr) = make_uint2(L0, L1);
}

// ---------------- BF16x3 GEMM-NT, 3-stage ring, 1 sync/iter, ldmatrix --------
#define SP2 12               // smem row stride in pairs (8 data + 4 pad)
#define GARR 1536            // words per array per stage (128*12)
#define GST  (4*GARR)        // 6144 words per stage
__global__ __launch_bounds__(256, 2) void bf16_gemm(
    const unsigned* __restrict__ Agh, const unsigned* __restrict__ Agl,
    const unsigned* __restrict__ B0h, const unsigned* __restrict__ B0l,
    const unsigned* __restrict__ B1h, const unsigned* __restrict__ B1l,
    const unsigned* __restrict__ B2h, const unsigned* __restrict__ B2l,
    unsigned* __restrict__ C0h, unsigned* __restrict__ C0l,
    unsigned* __restrict__ C1h, unsigned* __restrict__ C1l,
    unsigned* __restrict__ C2h, unsigned* __restrict__ C2l,
    float* __restrict__ Cf, int mode, const int* __restrict__ te,
    const float* __restrict__ aux1, const float* __restrict__ aux2)
{
    extern __shared__ unsigned gsm[];            // 3 * GST words = 73728 B

    const unsigned* Bgh = B0h; const unsigned* Bgl = B0l;
    unsigned* Ch = C0h; unsigned* Cl = C0l;
    float scale = 1.0f;
    if (mode == 4) {
        if (blockIdx.z == 1)      { Bgh = B1h; Bgl = B1l; Ch = C1h; Cl = C1l; }
        else if (blockIdx.z == 2) { Bgh = B2h; Bgl = B2l; Ch = C2h; Cl = C2l; }
        else                      { scale = 0.125f; }
    }

    const int t = threadIdx.x;
    const int row0 = blockIdx.y << 7, col0 = blockIdx.x << 7;
    const int lrow = t >> 1, lchunk = t & 1;
    const size_t aoff = ((size_t)(row0 + lrow) << 8) + (lchunk << 2);
    const size_t boff = ((size_t)(col0 + lrow) << 8) + (lchunk << 2);
    const unsigned cta = su32(gsm);
    const unsigned sbase = cta + (unsigned)((lrow * SP2 + (lchunk << 2)) << 2);

    const int warp = t >> 5, lane = t & 31;
    const int gid = lane >> 2, tig = lane & 3;
    const int wm = warp & 1, wn = warp >> 1;

    const int arowr = (wm << 6) + (lane & 15);
    const unsigned acolB = (unsigned)(lane & 16);
    const int browr = (wn << 5) + (lane & 7) + (((lane >> 4) & 1) << 3);
    const unsigned bcolB = (unsigned)(((lane >> 3) & 1) << 4);

    float acc[4][4][4];
#pragma unroll
    for (int mt = 0; mt < 4; mt++)
#pragma unroll
        for (int nt = 0; nt < 4; nt++)
#pragma unroll
            for (int r = 0; r < 4; r++) acc[mt][nt][r] = 0.f;

#define GLOAD(kt, st) do {                                   \
        const unsigned kc = (unsigned)(kt) << 3;             \
        const unsigned sd = sbase + (st) * (GST << 2);       \
        CP16(sd,                 Agh + aoff + kc);           \
        CP16(sd + (GARR << 2),   Agl + aoff + kc);           \
        CP16(sd + (2*GARR << 2), Bgh + boff + kc);           \
        CP16(sd + (3*GARR << 2), Bgl + boff + kc);           \
    } while (0)

    GLOAD(0, 0); CP_COMMIT();
    GLOAD(1, 1); CP_COMMIT();

    for (int kt = 0; kt < 32; kt++) {
        CP_WAIT1();
        __syncthreads();     // stage kt visible; compute(kt-1) done (ring hazard)
        if (kt + 2 < 32) GLOAD(kt + 2, (kt + 2) % 3);
        CP_COMMIT();

        const unsigned stB = cta + (unsigned)((kt % 3) * (GST << 2));

        unsigned bh[4][2], bl[4][2];
#pragma unroll
        for (int ntp = 0; ntp < 2; ntp++) {
            const unsigned ba = stB +
                (((2*GARR) + (browr + (ntp << 4)) * SP2) << 2) + bcolB;
            ldsm_x4(bh[2*ntp][0], bh[2*ntp][1], bh[2*ntp+1][0], bh[2*ntp+1][1], ba);
            ldsm_x4(bl[2*ntp][0], bl[2*ntp][1], bl[2*ntp+1][0], bl[2*ntp+1][1],
                    ba + (GARR << 2));
        }
#pragma unroll
        for (int mt = 0; mt < 4; mt++) {
            const unsigned aa = stB + (((arowr + (mt << 4)) * SP2) << 2) + acolB;
            unsigned ah[4], al[4];
            ldsm_x4(ah[0], ah[1], ah[2], ah[3], aa);
            ldsm_x4(al[0], al[1], al[2], al[3], aa + (GARR << 2));
#pragma unroll
            for (int nt = 0; nt < 4; nt++) {
                mma16(acc[mt][nt], al, bh[nt]);
                mma16(acc[mt][nt], ah, bl[nt]);
                mma16(acc[mt][nt], ah, bh[nt]);
            }
        }
    }

    // ---- epilogue ----
    if (mode == 3) {
#pragma unroll
        for (int mt = 0; mt < 4; mt++) {
            const int r1 = row0 + (wm << 6) + (mt << 4) + gid;
            const int r2 = r1 + 8;
#pragma unroll
            for (int nt = 0; nt < 4; nt++) {
                const int c = col0 + (wn << 5) + (nt << 3) + (tig << 1);
                const float a0 = aux1[c], a1 = aux1[c + 1];
                float v0 = acc[mt][nt][0] + a0 + aux2[((size_t)r1 << 9) + c];
                float v1 = acc[mt][nt][1] + a1 + aux2[((size_t)r1 << 9) + c + 1];
                float v2 = acc[mt][nt][2] + a0 + aux2[((size_t)r2 << 9) + c];
                float v3 = acc[mt][nt][3] + a1 + aux2[((size_t)r2 << 9) + c + 1];
                *(float2*)(Cf + ((size_t)r1 << 9) + c) = make_float2(v0, v1);
                *(float2*)(Cf + ((size_t)r2 << 9) + c) = make_float2(v2, v3);
            }
        }
    } else {
        int e = 0;
        if (mode == 0) e = te[row0 >> 10];
#pragma unroll
        for (int mt = 0; mt < 4; mt++) {
            const int r1 = row0 + (wm << 6) + (mt << 4) + gid;
            const int r2 = r1 + 8;
#pragma unroll
            for (int nt = 0; nt < 4; nt++) {
                const int c = col0 + (wn << 5) + (nt << 3) + (tig << 1);
                float a0 = 0.f, a1 = 0.f;
                if (mode == 0) {
                    a0 = aux1[((size_t)e << 9) + c];
                    a1 = aux1[((size_t)e << 9) + c + 1];
                }
                const float v0 = acc[mt][nt][0] * scale + a0;
                const float v1 = acc[mt][nt][1] * scale + a1;
                const float v2 = acc[mt][nt][2] * scale + a0;
                const float v3 = acc[mt][nt][3] * scale + a1;
                unsigned H, L;
                const size_t i0p = ((size_t)r1 << 8) + (c >> 1);
                const size_t i1p = ((size_t)r2 << 8) + (c >> 1);
                hl2(v0, v1, H, L); Ch[i0p] = H; Cl[i0p] = L;
                hl2(v2, v3, H, L); Ch[i1p] = H; Cl[i1p] = L;
            }
        }
    }
}

// ---------------- FA2-style bf16x3 attention, static 36KB smem ---------------
// (unchanged from round 7/8 — proven)
#define RS 36
#define STW 4608
__global__ __launch_bounds__(128, 2) void k_attn5(
    const unsigned* __restrict__ qh, const unsigned* __restrict__ ql,
    const unsigned* __restrict__ kh, const unsigned* __restrict__ kl,
    const unsigned* __restrict__ vh, const unsigned* __restrict__ vl,
    unsigned* __restrict__ aoh, unsigned* __restrict__ aol)
{
    __shared__ unsigned smw[2 * STW];

    const int jt = (gridDim.x - 1) - blockIdx.x;
    const int h = blockIdx.y, b = blockIdx.z;
    const int j0 = jt << 6;
    const int t = threadIdx.x, warp = t >> 5, lane = t & 31;
    const int gid = lane >> 2, tig = lane & 3;
    const size_t rowb = ((size_t)b << 10);
    const int coff2 = h << 5;
    const unsigned sbase = su32(smw);

    const int lrow = t >> 2;
    const int lsub = (t & 3) << 3;

#define LOADQV(i0_, st_) do {                                                   \
        const size_t g_ = ((rowb + (unsigned)(i0_) + lrow) << 8) + coff2 + lsub; \
        const unsigned s_ = sbase + (((st_) * STW + lrow * RS + lsub) << 2);     \
        CP16(s_,                  qh + g_);                                     \
        CP16(s_ + 16,             qh + g_ + 4);                                 \
        CP16(s_ + (1152 << 2),      ql + g_);                                   \
        CP16(s_ + (1152 << 2) + 16, ql + g_ + 4);                               \
        CP16(s_ + (2304 << 2),      vh + g_);                                   \
        CP16(s_ + (2304 << 2) + 16, vh + g_ + 4);                               \
        CP16(s_ + (3456 << 2),      vl + g_);                                   \
        CP16(s_ + (3456 << 2) + 16, vl + g_ + 4);                               \
    } while (0)

    const int ntiles = (jt << 1) + 2;

    LOADQV(0, 0); CP_COMMIT();
    if (ntiles > 1) LOADQV(32, 1);
    CP_COMMIT();

    const int krow = j0 + (warp << 4) + gid;
    const size_t kg0 = ((rowb + krow) << 8) + coff2;
    const size_t kg8 = ((rowb + krow + 8) << 8) + coff2;
    unsigned kfh[4][4], kfl[4][4];
#pragma unroll
    for (int ks = 0; ks < 4; ks++) {
        const int p = (ks << 3) + tig;
        kfh[ks][0] = kh[kg0 + p];     kfh[ks][1] = kh[kg8 + p];
        kfh[ks][2] = kh[kg0 + p + 4]; kfh[ks][3] = kh[kg8 + p + 4];
        kfl[ks][0] = kl[kg0 + p];     kfl[ks][1] = kl[kg8 + p];
        kfl[ks][2] = kl[kg0 + p + 4]; kfl[ks][3] = kl[kg8 + p + 4];
    }

    const int qrowrel = (lane & 7) + ((lane & 16) >> 1);
    const unsigned qcol = (lane & 8) >> 1;
    const int vrowrel = (lane & 7) + (lane & 8);
    const unsigned vcol = (lane & 16) >> 2;

    float m0 = NEGF, m1 = NEGF, l0 = 0.f, l1 = 0.f;
    float acc[8][4];
#pragma unroll
    for (int nb = 0; nb < 8; nb++)
#pragma unroll
        for (int r = 0; r < 4; r++) acc[nb][r] = 0.f;

    const int jr0 = j0 + (warp << 4) + gid, jr1 = jr0 + 8;

    for (int it = 0; it < ntiles; ++it) {
        CP_WAIT1();
        __syncthreads();
        const unsigned stw = (it & 1) * STW;

        float s[4][4];
#pragma unroll
        for (int nb = 0; nb < 4; nb++)
#pragma unroll
            for (int r = 0; r < 4; r++) s[nb][r] = 0.f;
#pragma unroll
        for (int ks = 0; ks < 4; ks++) {
#pragma unroll
            for (int nbp = 0; nbp < 2; nbp++) {
                const unsigned qa = sbase +
                    ((stw + ((nbp << 4) + qrowrel) * RS + (ks << 3) + qcol) << 2);
                unsigned q0, q1, q2, q3, w0, w1, w2, w3;
                ldsm_x4(q0, q1, q2, q3, qa);
                ldsm_x4(w0, w1, w2, w3, qa + (1152 << 2));
                unsigned bh0[2] = {q0, q1}, bh1[2] = {q2, q3};
                unsigned bl0[2] = {w0, w1}, bl1[2] = {w2, w3};
                mma16(s[2*nbp],     kfl[ks], bh0);
                mma16(s[2*nbp],     kfh[ks], bl0);
                mma16(s[2*nbp],     kfh[ks], bh0);
                mma16(s[2*nbp + 1], kfl[ks], bh1);
                mma16(s[2*nbp + 1], kfh[ks], bl1);
                mma16(s[2*nbp + 1], kfh[ks], bh1);
            }
        }

        if (it >= ntiles - 2) {
            const int i0 = it << 5;
#pragma unroll
            for (int nb = 0; nb < 4; nb++) {
                const int c = i0 + (nb << 3) + (tig << 1);
                if (c     > jr0) s[nb][0] = NEGF;
                if (c + 1 > jr0) s[nb][1] = NEGF;
                if (c     > jr1) s[nb][2] = NEGF;
                if (c + 1 > jr1) s[nb][3] = NEGF;
            }
        }

        float mt0 = NEGF, mt1 = NEGF;
#pragma unroll
        for (int nb = 0; nb < 4; nb++) {
            mt0 = fmaxf(mt0, fmaxf(s[nb][0], s[nb][1]));
            mt1 = fmaxf(mt1, fmaxf(s[nb][2], s[nb][3]));
        }
        mt0 = fmaxf(mt0, __shfl_xor_sync(0xffffffffu, mt0, 1));
        mt0 = fmaxf(mt0, __shfl_xor_sync(0xffffffffu, mt0, 2));
        mt1 = fmaxf(mt1, __shfl_xor_sync(0xffffffffu, mt1, 1));
        mt1 = fmaxf(mt1, __shfl_xor_sync(0xffffffffu, mt1, 2));
        const float mn0 = fmaxf(m0, mt0), mn1 = fmaxf(m1, mt1);
        const float sc0 = __expf(m0 - mn0), sc1 = __expf(m1 - mn1);
        m0 = mn0; m1 = mn1;

        float rs0 = 0.f, rs1 = 0.f;
#pragma unroll
        for (int nb = 0; nb < 4; nb++) {
            s[nb][0] = __expf(s[nb][0] - mn0);
            s[nb][1] = __expf(s[nb][1] - mn0);
            s[nb][2] = __expf(s[nb][2] - mn1);
            s[nb][3] = __expf(s[nb][3] - mn1);
            rs0 += s[nb][0] + s[nb][1];
            rs1 += s[nb][2] + s[nb][3];
        }
        rs0 += __shfl_xor_sync(0xffffffffu, rs0, 1);
        rs0 += __shfl_xor_sync(0xffffffffu, rs0, 2);
        rs1 += __shfl_xor_sync(0xffffffffu, rs1, 1);
        rs1 += __shfl_xor_sync(0xffffffffu, rs1, 2);
        l0 = l0 * sc0 + rs0;
        l1 = l1 * sc1 + rs1;

#pragma unroll
        for (int nb = 0; nb < 8; nb++) {
            acc[nb][0] *= sc0; acc[nb][1] *= sc0;
            acc[nb][2] *= sc1; acc[nb][3] *= sc1;
        }

#pragma unroll
        for (int kk = 0; kk < 2; kk++) {
            unsigned pah[4], pal[4];
            hl2(s[2*kk][0],     s[2*kk][1],     pah[0], pal[0]);
            hl2(s[2*kk][2],     s[2*kk][3],     pah[1], pal[1]);
            hl2(s[2*kk + 1][0], s[2*kk + 1][1], pah[2], pal[2]);
            hl2(s[2*kk + 1][2], s[2*kk + 1][3], pah[3], pal[3]);
#pragma unroll
            for (int nbp = 0; nbp < 4; nbp++) {
                const unsigned va = sbase +
                    ((stw + 2304 + ((kk << 4) + vrowrel) * RS + (nbp << 3) + vcol) << 2);
                unsigned v0, v1, v2, v3, w0, w1, w2, w3;
                ldsm_x4t(v0, v1, v2, v3, va);
                ldsm_x4t(w0, w1, w2, w3, va + (1152 << 2));
                unsigned vb0[2] = {v0, v1}, vb1[2] = {v2, v3};
                unsigned wb0[2] = {w0, w1}, wb1[2] = {w2, w3};
                mma16(acc[2*nbp],     pal, vb0);
                mma16(acc[2*nbp],     pah, wb0);
                mma16(acc[2*nbp],     pah, vb0);
                mma16(acc[2*nbp + 1], pal, vb1);
                mma16(acc[2*nbp + 1], pah, wb1);
                mma16(acc[2*nbp + 1], pah, vb1);
            }
        }

        __syncthreads();
        if (it + 2 < ntiles) LOADQV((it + 2) << 5, it & 1);
        CP_COMMIT();
    }

    const float rl0 = 1.0f / l0, rl1 = 1.0f / l1;
    const size_t o1 = ((rowb + jr0) << 8) + coff2;
    const size_t o2 = ((rowb + jr1) << 8) + coff2;
#pragma unroll
    for (int nb = 0; nb < 8; nb++) {
        const int pp = (nb << 2) + tig;
        unsigned H, L;
        hl2(acc[nb][0] * rl0, acc[nb][1] * rl0, H, L);
        aoh[o1 + pp] = H; aol[o1 + pp] = L;
        hl2(acc[nb][2] * rl1, acc[nb][3] * rl1, H, L);
        aoh[o2 + pp] = H; aol[o2 + pp] = L;
    }
#undef LOADQV
}

// ---------------- kernel 4: LN2 + coalesced transpose to (B,D,S) -------------
// Block = (b, 16 s-rows). Stage rows in smem, LN stats per row, then write
// transposed with 16 consecutive lanes sharing d -> 64B coalesced stores.
__global__ __launch_bounds__(256) void k_ln2t(
    const float* __restrict__ res, const float* __restrict__ g2,
    const float* __restrict__ b2, float* __restrict__ out)
{
    __shared__ float sm[16 * 513];
    __shared__ float smean[16], srstd[16];

    const int blk = blockIdx.x;              // 0..1023
    const int b = blk >> 6, s0 = (blk & 63) << 4;
    const int t = threadIdx.x;

    // stage 16 rows x 512 (coalesced float4 loads)
    for (int i = t; i < 2048; i += 256) {
        const int r = i >> 7, c4 = (i & 127) << 2;
        const float4 v = *(const float4*)(res + ((size_t)((b << 10) + s0 + r) << 9) + c4);
        float* d = sm + r * 513 + c4;
        d[0] = v.x; d[1] = v.y; d[2] = v.z; d[3] = v.w;
    }
    __syncthreads();

    // per-row stats: 16 threads per row
    {
        const int r = t >> 4, tr = t & 15;
        float s1 = 0.f, s2 = 0.f;
        for (int k = tr; k < 512; k += 16) {
            const float x = sm[r * 513 + k];
            s1 += x; s2 += x * x;
        }
#pragma unroll
        for (int o = 8; o; o >>= 1) {
            s1 += __shfl_down_sync(0xffffffffu, s1, o, 16);
            s2 += __shfl_down_sync(0xffffffffu, s2, o, 16);
        }
        if (tr == 0) {
            const float mean = s1 * (1.0f / 512.0f);
            const float var  = (s2 - 512.0f * mean * mean) * (1.0f / 511.0f);
            smean[r] = mean;
            srstd[r] = rsqrtf(var + 1e-5f);
        }
    }
    __syncthreads();

    // transposed write: i = d*16 + si ; lanes 0..15 share d -> coalesced
    const float gg = g2[s0 + (t & 15)], be = b2[s0 + (t & 15)];
    for (int i = t; i < 8192; i += 256) {
        const int d = i >> 4, si = i & 15;
        const float x = sm[si * 513 + d];
        out[((size_t)((b << 9) + d) << 10) + s0 + si] =
            gg * (x - smean[si]) * srstd[si] + be;
    }
}

// ---------------- launch -----------------------------------------------------
extern "C" void kernel_launch(void* const* d_in, const int* in_sizes, int n_in,
                              void* d_out, int out_size)
{
    const float* ts     = (const float*)d_in[0];
    const int*   te     = (const int*)  d_in[1];
    const float* conv_w = (const float*)d_in[2];
    const float* conv_b = (const float*)d_in[3];
    const float* pe     = (const float*)d_in[4];
    const float* ts_emb = (const float*)d_in[5];
    const float* g1     = (const float*)d_in[6];
    const float* b1     = (const float*)d_in[7];
    const float* Mw     = (const float*)d_in[8];
    const float* Wq     = (const float*)d_in[9];
    const float* Wk     = (const float*)d_in[10];
    const float* Wv     = (const float*)d_in[11];
    const float* Wo     = (const float*)d_in[12];
    const float* bo     = (const float*)d_in[13];
    const float* g2     = (const float*)d_in[14];
    const float* b2     = (const float*)d_in[15];
    float* out = (float*)d_out;

    float *pc, *pr;
    unsigned *n1h, *n1l, *dh, *dl, *pqh, *pql, *pkh, *pkl, *pvh, *pvl, *ah, *al;
    unsigned *wmh, *wml, *wqh, *wql, *wkh, *wkl, *wvh, *wvl, *woh, *wol;
    cudaGetSymbolAddress((void**)&pc,  g_conv);
    cudaGetSymbolAddress((void**)&pr,  g_res);
    cudaGetSymbolAddress((void**)&n1h, g_n1h); cudaGetSymbolAddress((void**)&n1l, g_n1l);
    cudaGetSymbolAddress((void**)&dh,  g_dh);  cudaGetSymbolAddress((void**)&dl,  g_dl);
    cudaGetSymbolAddress((void**)&pqh, g_qh);  cudaGetSymbolAddress((void**)&pql, g_ql);
    cudaGetSymbolAddress((void**)&pkh, g_kh);  cudaGetSymbolAddress((void**)&pkl, g_kl);
    cudaGetSymbolAddress((void**)&pvh, g_vh);  cudaGetSymbolAddress((void**)&pvl, g_vl);
    cudaGetSymbolAddress((void**)&ah,  g_ah);  cudaGetSymbolAddress((void**)&al,  g_al);
    cudaGetSymbolAddress((void**)&wmh, g_wmh); cudaGetSymbolAddress((void**)&wml, g_wml);
    cudaGetSymbolAddress((void**)&wqh, g_wqh); cudaGetSymbolAddress((void**)&wql, g_wql);
    cudaGetSymbolAddress((void**)&wkh, g_wkh); cudaGetSymbolAddress((void**)&wkl, g_wkl);
    cudaGetSymbolAddress((void**)&wvh, g_wvh); cudaGetSymbolAddress((void**)&wvl, g_wvl);
    cudaGetSymbolAddress((void**)&woh, g_woh); cudaGetSymbolAddress((void**)&wol, g_wol);

    const int GEMM_SMEM = 3 * GST * 4;           // 73728
    cudaFuncSetAttribute(bf16_gemm, cudaFuncAttributeMaxDynamicSharedMemorySize, GEMM_SMEM);

    // weight packing (once per launch)
    const int n4 = DDIM * DDIM / 4;
    CvtTab tab;
    tab.in[0] = (const float4*)Mw; tab.oh[0] = (uint2*)wmh; tab.ol[0] = (uint2*)wml;
    tab.in[1] = (const float4*)Wq; tab.oh[1] = (uint2*)wqh; tab.ol[1] = (uint2*)wql;
    tab.in[2] = (const float4*)Wk; tab.oh[2] = (uint2*)wkh; tab.ol[2] = (uint2*)wkl;
    tab.in[3] = (const float4*)Wv; tab.oh[3] = (uint2*)wvh; tab.ol[3] = (uint2*)wvl;
    tab.in[4] = (const float4*)Wo; tab.oh[4] = (uint2*)woh; tab.ol[4] = (uint2*)wol;
    k_cvt5<<<dim3(n4 / 256, 5), 256>>>(tab, n4);

    k_embed<<<BSN, 128>>>(ts, conv_w, conv_b, pe, g1, b1, pc, n1h, n1l);

    dim3 gg(4, 128, 1);
    bf16_gemm<<<gg, 256, GEMM_SMEM>>>(n1h, n1l, wmh, wml, nullptr, nullptr, nullptr, nullptr,
                                      dh, dl, nullptr, nullptr, nullptr, nullptr,
                                      nullptr, 0, te, ts_emb, nullptr);
    dim3 gq(4, 128, 3);
    bf16_gemm<<<gq, 256, GEMM_SMEM>>>(dh, dl, wqh, wql, wkh, wkl, wvh, wvl,
                                      pqh, pql, pkh, pkl, pvh, pvl,
                                      nullptr, 4, nullptr, nullptr, nullptr);

    k_attn5<<<dim3(SSZ / 64, 8, BB), 128>>>(pqh, pql, pkh, pkl, pvh, pvl, ah, al);

    bf16_gemm<<<gg, 256, GEMM_SMEM>>>(ah, al, woh, wol, nullptr, nullptr, nullptr, nullptr,
                                      nullptr, nullptr, nullptr, nullptr, nullptr, nullptr,
                                      pr, 3, nullptr, bo, pc);

    k_ln2t<<<BB * 64, 256>>>(pr, g2, b2, out);
}